// round 9
// baseline (speedup 1.0000x reference)
#include <cuda_runtime.h>
#include <cstdint>
#include <math.h>

// ---------------------------------------------------------------- constants
#define BB   2
#define SS   2048
#define HIDD 2048
#define NH   32
#define NKV  8
#define DH   64
#define MROWS (BB*SS)        // 4096
#define KVDIM (NKV*DH)       // 512
#define KDIM  2048
#define QKVDIM (HIDD + 2*KVDIM)   // 3072

typedef unsigned long long u64t;

// ---------------------------------------------------------------- scratch
__device__ float g_qkv[(size_t)MROWS * QKVDIM];   // 48 MB (q | k | v per row)
__device__ float g_at [(size_t)MROWS * HIDD];     // 32 MB

// ---------------------------------------------------------------- f32x2 helpers
__device__ __forceinline__ u64t pack2(float lo, float hi) {
    u64t d; asm("mov.b64 %0, {%1, %2};" : "=l"(d) : "f"(lo), "f"(hi)); return d;
}
__device__ __forceinline__ u64t pack_dup(float x) {
    u64t d; asm("mov.b64 %0, {%1, %1};" : "=l"(d) : "f"(x)); return d;
}
__device__ __forceinline__ void unpack2(u64t v, float& lo, float& hi) {
    asm("mov.b64 {%0, %1}, %2;" : "=f"(lo), "=f"(hi) : "l"(v));
}
__device__ __forceinline__ u64t fma2(u64t a, u64t b, u64t c) {
    u64t d; asm("fma.rn.f32x2 %0, %1, %2, %3;" : "=l"(d) : "l"(a), "l"(b), "l"(c)); return d;
}
__device__ __forceinline__ u64t mul2(u64t a, u64t b) {
    u64t d; asm("mul.rn.f32x2 %0, %1, %2;" : "=l"(d) : "l"(a), "l"(b)); return d;
}

// ---------------------------------------------------------------- GEMM (f32x2, A pre-dup in smem)
// C[M,N] = A[M,K] * B[N,K]^T, K = KDIM. B rows sourced from up to 3 arrays
// (merged QKV weights) split at n1 / n2. 128x128x32 tile, 256 threads,
// 8x8 micro-tile packed along N as 8x4 f32x2.
#define BM 128
#define BN 128
#define BK 32
#define BM2 258            // duplicated A row: 2*128 + 2 pad (floats)
#define BNP 132            // B row: 128 + 4 pad (floats)
#define GSMEM ((BK*BM2 + BK*BNP) * 4)   // 49920 B

__global__ __launch_bounds__(256) void gemm_f32x2(
    const float* __restrict__ A,
    const float* __restrict__ B0, const float* __restrict__ B1,
    const float* __restrict__ B2, int n1, int n2,
    float* __restrict__ C, int N)
{
    extern __shared__ __align__(16) float smem[];
    float* smA = smem;                 // [BK][BM2]  A duplicated
    float* smB = smem + BK * BM2;      // [BK][BNP]  B transposed

    const int tid = threadIdx.x;
    const int bm = blockIdx.y * BM;
    const int bn = blockIdx.x * BN;
    const int ty = tid >> 4;          // 0..15
    const int tx = tid & 15;          // 0..15

    // loaders: 32 rows per pass, 8 threads per row, float4 each
    const int lr = tid >> 3;          // 0..31
    const int lc = (tid & 7) << 2;    // 0,4,...,28

    // per-pass source pointers (row fixed across k iterations)
    const float* Ap[4];
    const float* Bp[4];
#pragma unroll
    for (int p = 0; p < 4; p++) {
        Ap[p] = A + (size_t)(bm + p * 32 + lr) * KDIM;
        int n = bn + p * 32 + lr;
        Bp[p] = (n < n1) ? B0 + (size_t)n * KDIM
              : (n < n2) ? B1 + (size_t)(n - n1) * KDIM
                         : B2 + (size_t)(n - n2) * KDIM;
    }

    u64t acc2[8][4];
#pragma unroll
    for (int i = 0; i < 8; i++)
#pragma unroll
        for (int j = 0; j < 4; j++) acc2[i][j] = pack2(0.f, 0.f);

    for (int k0 = 0; k0 < KDIM; k0 += BK) {
#pragma unroll
        for (int p = 0; p < 4; p++) {
            const int row = p * 32 + lr;
            float4 va = *(const float4*)(Ap[p] + k0 + lc);
            ((float2*)&smA[(lc + 0) * BM2 + 2 * row])[0] = make_float2(va.x, va.x);
            ((float2*)&smA[(lc + 1) * BM2 + 2 * row])[0] = make_float2(va.y, va.y);
            ((float2*)&smA[(lc + 2) * BM2 + 2 * row])[0] = make_float2(va.z, va.z);
            ((float2*)&smA[(lc + 3) * BM2 + 2 * row])[0] = make_float2(va.w, va.w);
            float4 vb = *(const float4*)(Bp[p] + k0 + lc);
            smB[(lc + 0) * BNP + row] = vb.x;
            smB[(lc + 1) * BNP + row] = vb.y;
            smB[(lc + 2) * BNP + row] = vb.z;
            smB[(lc + 3) * BNP + row] = vb.w;
        }
        __syncthreads();

#pragma unroll
        for (int kk = 0; kk < BK; kk++) {
            const float* aRow = &smA[kk * BM2 + ty * 16];   // 2*(ty*8)
            u64t ad[8];
#pragma unroll
            for (int i = 0; i < 8; i++)
                ad[i] = *(const u64t*)(aRow + 2 * i);
            ulonglong2 b01 = *(const ulonglong2*)&smB[kk * BNP + tx * 8];
            ulonglong2 b23 = *(const ulonglong2*)&smB[kk * BNP + tx * 8 + 4];
            u64t bv[4] = { b01.x, b01.y, b23.x, b23.y };
#pragma unroll
            for (int i = 0; i < 8; i++)
#pragma unroll
                for (int j = 0; j < 4; j++)
                    acc2[i][j] = fma2(ad[i], bv[j], acc2[i][j]);
        }
        __syncthreads();
    }

#pragma unroll
    for (int i = 0; i < 8; i++) {
        float* cp = C + (size_t)(bm + ty * 8 + i) * N + bn + tx * 8;
        ulonglong2 v0 = { acc2[i][0], acc2[i][1] };
        ulonglong2 v1 = { acc2[i][2], acc2[i][3] };
        *(ulonglong2*)cp       = v0;
        *(ulonglong2*)(cp + 4) = v1;
    }
}

// ---------------------------------------------------------------- RoPE (merged qkv strides)
__global__ void rope_kernel(float* __restrict__ qkv,
                            const float* __restrict__ cs, const float* __restrict__ sn)
{
    const int QP = MROWS * NH  * (DH / 2);
    const int KP = MROWS * NKV * (DH / 2);
    int idx = blockIdx.x * blockDim.x + threadIdx.x;
    if (idx < QP) {
        int d = idx & 31;
        int h = (idx >> 5) & (NH - 1);
        int r = idx >> 10;
        float c = cs[r * DH + d], s = sn[r * DH + d];
        float* p = qkv + (size_t)r * QKVDIM + h * DH + d;
        float x1 = p[0], x2 = p[32];
        p[0]  = x1 * c - x2 * s;
        p[32] = x2 * c + x1 * s;
    } else if (idx < QP + KP) {
        int j = idx - QP;
        int d = j & 31;
        int h = (j >> 5) & (NKV - 1);
        int r = j >> 8;
        float c = cs[r * DH + d], s = sn[r * DH + d];
        float* p = qkv + (size_t)r * QKVDIM + HIDD + h * DH + d;
        float x1 = p[0], x2 = p[32];
        p[0]  = x1 * c - x2 * s;
        p[32] = x2 * c + x1 * s;
    }
}

// ---------------------------------------------------------------- attention (f32x2, R8)
#define AQ 128
#define AK 32
#define KPAD 68

__global__ __launch_bounds__(128) void attn_kernel(
    const float* __restrict__ QKV, float* __restrict__ O)
{
    __shared__ float Ks[AK][KPAD];
    __shared__ float Vs[AK][KPAD];

    const int tid = threadIdx.x;
    const int b   = blockIdx.y >> 5;
    const int h   = blockIdx.y & 31;
    const int kvh = h >> 2;
    const int qrow = blockIdx.x * AQ + tid;

    const float scale = 0.125f;
    const float* qp = QKV + (size_t)(b * SS + qrow) * QKVDIM + h * DH;

    u64t q2[DH / 2], o2[DH / 2];
#pragma unroll
    for (int i = 0; i < DH / 4; i++) {
        float4 v = *(const float4*)(qp + 4 * i);
        q2[2 * i + 0] = pack2(v.x * scale, v.y * scale);
        q2[2 * i + 1] = pack2(v.z * scale, v.w * scale);
        o2[2 * i + 0] = pack2(0.f, 0.f);
        o2[2 * i + 1] = pack2(0.f, 0.f);
    }

    float m = -1e30f, l = 0.f;
    const int nt = (blockIdx.x * AQ + AQ) / AK;

    const int lj   = tid >> 2;
    const int loff = (tid & 3) << 2;

    for (int t = 0; t < nt; t++) {
        const int k0 = t * AK;
        __syncthreads();
        {
            const float* kp = QKV + (size_t)(b * SS + k0 + lj) * QKVDIM + HIDD + kvh * DH;
            const float* vp = kp + KVDIM;
#pragma unroll
            for (int i = 0; i < 4; i++) {
                int c = loff + 16 * i;
                *(float4*)&Ks[lj][c] = *(const float4*)(kp + c);
                *(float4*)&Vs[lj][c] = *(const float4*)(vp + c);
            }
        }
        __syncthreads();

        float s[AK];
        float tmax = -1e30f;
#pragma unroll
        for (int j = 0; j < AK; j++) {
            u64t acc = pack2(0.f, 0.f);
#pragma unroll
            for (int d = 0; d < DH / 4; d++) {
                ulonglong2 kk2 = *(const ulonglong2*)&Ks[j][4 * d];
                acc = fma2(q2[2 * d + 0], kk2.x, acc);
                acc = fma2(q2[2 * d + 1], kk2.y, acc);
            }
            float alo, ahi;
            unpack2(acc, alo, ahi);
            float sc = alo + ahi;
            sc = (k0 + j <= qrow) ? sc : -1e30f;
            s[j] = sc;
            tmax = fmaxf(tmax, sc);
        }

        if (tmax > m) {
            float mn = tmax;
            float corr = __expf(m - mn);
            m = mn;
            l *= corr;
            u64t cd = pack_dup(corr);
#pragma unroll
            for (int d = 0; d < DH / 2; d++) o2[d] = mul2(o2[d], cd);
        }

#pragma unroll
        for (int j = 0; j < AK; j++) {
            float p = __expf(s[j] - m);
            l += p;
            u64t pd = pack_dup(p);
#pragma unroll
            for (int d = 0; d < DH / 4; d++) {
                ulonglong2 v2 = *(const ulonglong2*)&Vs[j][4 * d];
                o2[2 * d + 0] = fma2(pd, v2.x, o2[2 * d + 0]);
                o2[2 * d + 1] = fma2(pd, v2.y, o2[2 * d + 1]);
            }
        }
    }

    const float inv = 1.f / l;
    float* op = O + (size_t)(b * SS + qrow) * HIDD + h * DH;
#pragma unroll
    for (int d = 0; d < DH / 4; d++) {
        float x0, x1, x2, x3;
        unpack2(o2[2 * d + 0], x0, x1);
        unpack2(o2[2 * d + 1], x2, x3);
        float4 v = { x0 * inv, x1 * inv, x2 * inv, x3 * inv };
        *(float4*)(op + 4 * d) = v;
    }
}

// ---------------------------------------------------------------- launch
extern "C" void kernel_launch(void* const* d_in, const int* in_sizes, int n_in,
                              void* d_out, int out_size)
{
    const float* hs = (const float*)d_in[0];
    const float* cs = (const float*)d_in[1];
    const float* sn = (const float*)d_in[2];
    const float* Wq = (const float*)d_in[4];
    const float* Wk = (const float*)d_in[5];
    const float* Wv = (const float*)d_in[6];
    const float* Wo = (const float*)d_in[7];
    float* out = (float*)d_out;

    float *qkv, *at;
    cudaGetSymbolAddress((void**)&qkv, g_qkv);
    cudaGetSymbolAddress((void**)&at,  g_at);

    cudaFuncSetAttribute(gemm_f32x2, cudaFuncAttributeMaxDynamicSharedMemorySize, GSMEM);

    // merged QKV projection: rows [0,2048)=Wq, [2048,2560)=Wk, [2560,3072)=Wv
    gemm_f32x2<<<dim3(QKVDIM / BN, MROWS / BM), 256, GSMEM>>>(
        hs, Wq, Wk, Wv, HIDD, HIDD + KVDIM, qkv, QKVDIM);

    const int pairs = MROWS * NH * (DH / 2) + MROWS * NKV * (DH / 2);
    rope_kernel<<<pairs / 256, 256>>>(qkv, cs, sn);

    attn_kernel<<<dim3(SS / AQ, BB * NH), dim3(128)>>>(qkv, at);

    // output projection (single source: n1 = n2 = N)
    gemm_f32x2<<<dim3(HIDD / BN, MROWS / BM), 256, GSMEM>>>(
        at, Wo, Wo, Wo, HIDD, HIDD, out, HIDD);
}

// round 10
// speedup vs baseline: 1.7677x; 1.7677x over previous
#include <cuda_runtime.h>
#include <cuda_fp16.h>
#include <cstdint>
#include <math.h>

// ---------------------------------------------------------------- constants
#define BB   2
#define SS   2048
#define HIDD 2048
#define NH   32
#define NKV  8
#define DH   64
#define MROWS (BB*SS)        // 4096
#define KVDIM (NKV*DH)       // 512
#define KDIM  2048
#define K2   (2*KDIM)        // 4096: A expanded as [hi | lo]
#define QKVDIM (HIDD + 2*KVDIM)   // 3072

typedef unsigned long long u64t;

// ---------------------------------------------------------------- scratch
__device__ float g_qkv[(size_t)MROWS * QKVDIM];   // 48 MB
__device__ float g_at [(size_t)MROWS * HIDD];     // 32 MB

__device__ __half g_hs_e[(size_t)MROWS * K2];     // 32 MB [hi|lo]
__device__ __half g_w_h [(size_t)QKVDIM * KDIM];  // 12 MB fp16(W) merged q|k|v
__device__ __half g_wo_h[(size_t)HIDD  * KDIM];   //  8 MB
__device__ __half g_at_e[(size_t)MROWS * K2];     // 32 MB [hi|lo]

// ---------------------------------------------------------------- helpers
__device__ __forceinline__ uint32_t smem_u32(const void* p) {
    uint32_t a;
    asm("{ .reg .u64 t; cvta.to.shared.u64 t, %1; cvt.u32.u64 %0, t; }" : "=r"(a) : "l"(p));
    return a;
}
__device__ __forceinline__ void cpa16(uint32_t s, const void* g) {
    asm volatile("cp.async.cg.shared.global [%0], [%1], 16;" :: "r"(s), "l"(g));
}
__device__ __forceinline__ void cpa_commit() {
    asm volatile("cp.async.commit_group;" ::: "memory");
}
template<int N> __device__ __forceinline__ void cpa_wait() {
    asm volatile("cp.async.wait_group %0;" :: "n"(N) : "memory");
}
__device__ __forceinline__ void ldsm_x4(uint32_t& r0, uint32_t& r1, uint32_t& r2, uint32_t& r3,
                                        uint32_t addr) {
    asm volatile("ldmatrix.sync.aligned.m8n8.x4.shared.b16 {%0,%1,%2,%3}, [%4];"
                 : "=r"(r0), "=r"(r1), "=r"(r2), "=r"(r3) : "r"(addr));
}
__device__ __forceinline__ void mma_f16(float& c0, float& c1, float& c2, float& c3,
                                        uint32_t a0, uint32_t a1, uint32_t a2, uint32_t a3,
                                        uint32_t b0, uint32_t b1) {
    asm volatile(
        "mma.sync.aligned.m16n8k16.row.col.f32.f16.f16.f32 "
        "{%0,%1,%2,%3}, {%4,%5,%6,%7}, {%8,%9}, {%0,%1,%2,%3};"
        : "+f"(c0), "+f"(c1), "+f"(c2), "+f"(c3)
        : "r"(a0), "r"(a1), "r"(a2), "r"(a3), "r"(b0), "r"(b1));
}
// f32x2
__device__ __forceinline__ u64t pack2(float lo, float hi) {
    u64t d; asm("mov.b64 %0, {%1, %2};" : "=l"(d) : "f"(lo), "f"(hi)); return d;
}
__device__ __forceinline__ u64t pack_dup(float x) {
    u64t d; asm("mov.b64 %0, {%1, %1};" : "=l"(d) : "f"(x)); return d;
}
__device__ __forceinline__ void unpack2(u64t v, float& lo, float& hi) {
    asm("mov.b64 {%0, %1}, %2;" : "=f"(lo), "=f"(hi) : "l"(v));
}
__device__ __forceinline__ u64t fma2(u64t a, u64t b, u64t c) {
    u64t d; asm("fma.rn.f32x2 %0, %1, %2, %3;" : "=l"(d) : "l"(a), "l"(b), "l"(c)); return d;
}
__device__ __forceinline__ u64t mul2(u64t a, u64t b) {
    u64t d; asm("mul.rn.f32x2 %0, %1, %2;" : "=l"(d) : "l"(a), "l"(b)); return d;
}

// ---------------------------------------------------------------- expand / convert
// A' = [hi | lo] fp16 along K2; B converted to plain fp16 (GEMM wraps k).
__global__ void expandA_kernel(const float* __restrict__ s, __half* __restrict__ d, int M) {
    int idx = blockIdx.x * blockDim.x + threadIdx.x;
    if (idx >= M * KDIM) return;
    int m = idx / KDIM, k = idx - m * KDIM;
    float x = s[idx];
    __half hi = __float2half(x);
    __half lo = __float2half(x - __half2float(hi));
    __half* row = d + (size_t)m * K2;
    row[k] = hi; row[KDIM + k] = lo;
}
__global__ void convB_kernel(const float* __restrict__ s, __half* __restrict__ d, int n) {
    int idx = blockIdx.x * blockDim.x + threadIdx.x;
    if (idx < n) d[idx] = __float2half(s[idx]);
}

// ---------------------------------------------------------------- fp16 HMMA GEMM
// C[M,N] = A'[M,K2] * B[N,KDIM]^T with B k-offset wrapped mod KDIM:
// pass 1 (k<2048) uses Ahi, pass 2 (k>=2048) uses Alo, both against the same B.
#define BK3   32
#define NK2   (K2 / BK3)         // 128
#define SROWB 80
#define ATILE_B (128 * SROWB)
#define STAGE_B (2 * ATILE_B)
#define GSMEM  (3 * STAGE_B)

__global__ __launch_bounds__(256) void gemm_f16(
    const __half* __restrict__ A, const __half* __restrict__ B,
    float* __restrict__ C, int N)
{
    extern __shared__ __align__(128) char smem[];
    const uint32_t sb = smem_u32(smem);
    const int tid  = threadIdx.x;
    const int lane = tid & 31;
    const int wid  = tid >> 5;
    const int wm   = wid & 3;
    const int wn   = wid >> 2;
    const int bm = blockIdx.y * 128, bn = blockIdx.x * 128;

    const int lrow = tid >> 1;
    const int lc   = (tid & 1) * 2;
    const __half* Ab = A + (size_t)(bm + lrow) * K2 + lc * 8;
    const __half* Bb = B + (size_t)(bn + lrow) * KDIM + lc * 8;
    const uint32_t saA = sb + lrow * SROWB + lc * 16;
    const uint32_t saB = sb + ATILE_B + lrow * SROWB + lc * 16;

    float acc[2][8][4];
#pragma unroll
    for (int i = 0; i < 2; i++)
#pragma unroll
        for (int j = 0; j < 8; j++)
#pragma unroll
            for (int r = 0; r < 4; r++) acc[i][j][r] = 0.f;

    const int a_row = wm * 32 + (lane & 15);
    const int a_kb  = (lane >> 4) * 16;
    const int b_row = wn * 64 + ((lane >> 4) << 3) + (lane & 7);
    const int b_kb  = ((lane >> 3) & 1) * 16;

#pragma unroll
    for (int s = 0; s < 2; s++) {
        cpa16(saA + s * STAGE_B,      Ab + s * BK3);
        cpa16(saA + s * STAGE_B + 16, Ab + s * BK3 + 8);
        cpa16(saB + s * STAGE_B,      Bb + s * BK3);
        cpa16(saB + s * STAGE_B + 16, Bb + s * BK3 + 8);
        cpa_commit();
    }

    for (int kt = 0; kt < NK2; kt++) {
        cpa_wait<1>();
        __syncthreads();

        if (kt + 2 < NK2) {
            const int ps = (kt + 2) % 3;
            const int kA = (kt + 2) * BK3;
            const int kB = kA & (KDIM - 1);          // wrap B into [0, KDIM)
            cpa16(saA + ps * STAGE_B,      Ab + kA);
            cpa16(saA + ps * STAGE_B + 16, Ab + kA + 8);
            cpa16(saB + ps * STAGE_B,      Bb + kB);
            cpa16(saB + ps * STAGE_B + 16, Bb + kB + 8);
        }
        cpa_commit();

        const uint32_t sAs = sb + (kt % 3) * STAGE_B;
        const uint32_t sBs = sAs + ATILE_B;

#pragma unroll
        for (int kh = 0; kh < 2; kh++) {
            const int kbyte = kh * 32;
            uint32_t a[2][4];
#pragma unroll
            for (int mt = 0; mt < 2; mt++)
                ldsm_x4(a[mt][0], a[mt][1], a[mt][2], a[mt][3],
                        sAs + (a_row + mt * 16) * SROWB + kbyte + a_kb);
            uint32_t b[4][4];
#pragma unroll
            for (int nt = 0; nt < 4; nt++)
                ldsm_x4(b[nt][0], b[nt][1], b[nt][2], b[nt][3],
                        sBs + (b_row + nt * 16) * SROWB + kbyte + b_kb);
#pragma unroll
            for (int mt = 0; mt < 2; mt++)
#pragma unroll
                for (int j = 0; j < 8; j++)
                    mma_f16(acc[mt][j][0], acc[mt][j][1], acc[mt][j][2], acc[mt][j][3],
                            a[mt][0], a[mt][1], a[mt][2], a[mt][3],
                            b[j >> 1][(j & 1) * 2], b[j >> 1][(j & 1) * 2 + 1]);
        }
        __syncthreads();
    }

#pragma unroll
    for (int mt = 0; mt < 2; mt++) {
        int m0 = bm + wm * 32 + mt * 16 + (lane >> 2);
#pragma unroll
        for (int j = 0; j < 8; j++) {
            int n0 = bn + wn * 64 + j * 8 + (lane & 3) * 2;
            float2 v0 = { acc[mt][j][0], acc[mt][j][1] };
            float2 v1 = { acc[mt][j][2], acc[mt][j][3] };
            *(float2*)(C + (size_t)m0 * N + n0)       = v0;
            *(float2*)(C + (size_t)(m0 + 8) * N + n0) = v1;
        }
    }
}

// ---------------------------------------------------------------- RoPE (merged qkv strides)
__global__ void rope_kernel(float* __restrict__ qkv,
                            const float* __restrict__ cs, const float* __restrict__ sn)
{
    const int QP = MROWS * NH  * (DH / 2);
    const int KP = MROWS * NKV * (DH / 2);
    int idx = blockIdx.x * blockDim.x + threadIdx.x;
    if (idx < QP) {
        int d = idx & 31;
        int h = (idx >> 5) & (NH - 1);
        int r = idx >> 10;
        float c = cs[r * DH + d], s = sn[r * DH + d];
        float* p = qkv + (size_t)r * QKVDIM + h * DH + d;
        float x1 = p[0], x2 = p[32];
        p[0]  = x1 * c - x2 * s;
        p[32] = x2 * c + x1 * s;
    } else if (idx < QP + KP) {
        int j = idx - QP;
        int d = j & 31;
        int h = (j >> 5) & (NKV - 1);
        int r = j >> 8;
        float c = cs[r * DH + d], s = sn[r * DH + d];
        float* p = qkv + (size_t)r * QKVDIM + HIDD + h * DH + d;
        float x1 = p[0], x2 = p[32];
        p[0]  = x1 * c - x2 * s;
        p[32] = x2 * c + x1 * s;
    }
}

// ---------------------------------------------------------------- attention (f32x2, R8)
#define AQ 128
#define AK 32
#define KPAD 68

__global__ __launch_bounds__(128) void attn_kernel(
    const float* __restrict__ QKV, float* __restrict__ O)
{
    __shared__ float Ks[AK][KPAD];
    __shared__ float Vs[AK][KPAD];

    const int tid = threadIdx.x;
    const int b   = blockIdx.y >> 5;
    const int h   = blockIdx.y & 31;
    const int kvh = h >> 2;
    const int qrow = blockIdx.x * AQ + tid;

    const float scale = 0.125f;
    const float* qp = QKV + (size_t)(b * SS + qrow) * QKVDIM + h * DH;

    u64t q2[DH / 2], o2[DH / 2];
#pragma unroll
    for (int i = 0; i < DH / 4; i++) {
        float4 v = *(const float4*)(qp + 4 * i);
        q2[2 * i + 0] = pack2(v.x * scale, v.y * scale);
        q2[2 * i + 1] = pack2(v.z * scale, v.w * scale);
        o2[2 * i + 0] = pack2(0.f, 0.f);
        o2[2 * i + 1] = pack2(0.f, 0.f);
    }

    float m = -1e30f, l = 0.f;
    const int nt = (blockIdx.x * AQ + AQ) / AK;

    const int lj   = tid >> 2;
    const int loff = (tid & 3) << 2;

    for (int t = 0; t < nt; t++) {
        const int k0 = t * AK;
        __syncthreads();
        {
            const float* kp = QKV + (size_t)(b * SS + k0 + lj) * QKVDIM + HIDD + kvh * DH;
            const float* vp = kp + KVDIM;
#pragma unroll
            for (int i = 0; i < 4; i++) {
                int c = loff + 16 * i;
                *(float4*)&Ks[lj][c] = *(const float4*)(kp + c);
                *(float4*)&Vs[lj][c] = *(const float4*)(vp + c);
            }
        }
        __syncthreads();

        float s[AK];
        float tmax = -1e30f;
#pragma unroll
        for (int j = 0; j < AK; j++) {
            u64t acc = pack2(0.f, 0.f);
#pragma unroll
            for (int d = 0; d < DH / 4; d++) {
                ulonglong2 kk2 = *(const ulonglong2*)&Ks[j][4 * d];
                acc = fma2(q2[2 * d + 0], kk2.x, acc);
                acc = fma2(q2[2 * d + 1], kk2.y, acc);
            }
            float alo, ahi;
            unpack2(acc, alo, ahi);
            float sc = alo + ahi;
            sc = (k0 + j <= qrow) ? sc : -1e30f;
            s[j] = sc;
            tmax = fmaxf(tmax, sc);
        }

        if (tmax > m) {
            float mn = tmax;
            float corr = __expf(m - mn);
            m = mn;
            l *= corr;
            u64t cd = pack_dup(corr);
#pragma unroll
            for (int d = 0; d < DH / 2; d++) o2[d] = mul2(o2[d], cd);
        }

#pragma unroll
        for (int j = 0; j < AK; j++) {
            float p = __expf(s[j] - m);
            l += p;
            u64t pd = pack_dup(p);
#pragma unroll
            for (int d = 0; d < DH / 4; d++) {
                ulonglong2 v2 = *(const ulonglong2*)&Vs[j][4 * d];
                o2[2 * d + 0] = fma2(pd, v2.x, o2[2 * d + 0]);
                o2[2 * d + 1] = fma2(pd, v2.y, o2[2 * d + 1]);
            }
        }
    }

    const float inv = 1.f / l;
    float* op = O + (size_t)(b * SS + qrow) * HIDD + h * DH;
#pragma unroll
    for (int d = 0; d < DH / 4; d++) {
        float x0, x1, x2, x3;
        unpack2(o2[2 * d + 0], x0, x1);
        unpack2(o2[2 * d + 1], x2, x3);
        float4 v = { x0 * inv, x1 * inv, x2 * inv, x3 * inv };
        *(float4*)(op + 4 * d) = v;
    }
}

// ---------------------------------------------------------------- launch
extern "C" void kernel_launch(void* const* d_in, const int* in_sizes, int n_in,
                              void* d_out, int out_size)
{
    const float* hs = (const float*)d_in[0];
    const float* cs = (const float*)d_in[1];
    const float* sn = (const float*)d_in[2];
    const float* Wq = (const float*)d_in[4];
    const float* Wk = (const float*)d_in[5];
    const float* Wv = (const float*)d_in[6];
    const float* Wo = (const float*)d_in[7];
    float* out = (float*)d_out;

    float *qkv, *at;
    cudaGetSymbolAddress((void**)&qkv, g_qkv);
    cudaGetSymbolAddress((void**)&at,  g_at);
    __half *hse, *wh, *woh, *ate;
    cudaGetSymbolAddress((void**)&hse, g_hs_e);
    cudaGetSymbolAddress((void**)&wh,  g_w_h);
    cudaGetSymbolAddress((void**)&woh, g_wo_h);
    cudaGetSymbolAddress((void**)&ate, g_at_e);

    cudaFuncSetAttribute(gemm_f16, cudaFuncAttributeMaxDynamicSharedMemorySize, GSMEM);

    const int nHS = MROWS * KDIM, nWQ = HIDD * KDIM, nWK = KVDIM * KDIM;
    expandA_kernel<<<(nHS + 255) / 256, 256>>>(hs, hse, MROWS);
    convB_kernel<<<(nWQ + 255) / 256, 256>>>(Wq, wh, nWQ);
    convB_kernel<<<(nWK + 255) / 256, 256>>>(Wk, wh + (size_t)HIDD * KDIM, nWK);
    convB_kernel<<<(nWK + 255) / 256, 256>>>(Wv, wh + (size_t)(HIDD + KVDIM) * KDIM, nWK);
    convB_kernel<<<(nWQ + 255) / 256, 256>>>(Wo, woh, nWQ);

    // merged QKV projection
    gemm_f16<<<dim3(QKVDIM / 128, MROWS / 128), 256, GSMEM>>>(hse, wh, qkv, QKVDIM);

    const int pairs = MROWS * NH * (DH / 2) + MROWS * NKV * (DH / 2);
    rope_kernel<<<pairs / 256, 256>>>(qkv, cs, sn);

    attn_kernel<<<dim3(SS / AQ, BB * NH), dim3(128)>>>(qkv, at);

    expandA_kernel<<<(nHS + 255) / 256, 256>>>(at, ate, MROWS);
    gemm_f16<<<dim3(HIDD / 128, MROWS / 128), 256, GSMEM>>>(ate, woh, out, HIDD);
}

// round 11
// speedup vs baseline: 1.8233x; 1.0315x over previous
#include <cuda_runtime.h>
#include <cuda_fp16.h>
#include <cstdint>
#include <math.h>

// ---------------------------------------------------------------- constants
#define BB   2
#define SS   2048
#define HIDD 2048
#define NH   32
#define NKV  8
#define DH   64
#define MROWS (BB*SS)        // 4096
#define KVDIM (NKV*DH)       // 512
#define KDIM  2048
#define K2   (2*KDIM)        // 4096: A expanded as [hi | lo]
#define QKVDIM (HIDD + 2*KVDIM)   // 3072

typedef unsigned long long u64t;

// ---------------------------------------------------------------- scratch
__device__ float g_qkv[(size_t)MROWS * QKVDIM];   // 48 MB
__device__ __half g_hs_e[(size_t)MROWS * K2];     // 32 MB [hi|lo]
__device__ __half g_w_h [(size_t)QKVDIM * KDIM];  // 12 MB fp16(W) merged q|k|v
__device__ __half g_wo_h[(size_t)HIDD  * KDIM];   //  8 MB
__device__ __half g_at_e[(size_t)MROWS * K2];     // 32 MB [hi|lo]

// ---------------------------------------------------------------- helpers
__device__ __forceinline__ uint32_t smem_u32(const void* p) {
    uint32_t a;
    asm("{ .reg .u64 t; cvta.to.shared.u64 t, %1; cvt.u32.u64 %0, t; }" : "=r"(a) : "l"(p));
    return a;
}
__device__ __forceinline__ void cpa16(uint32_t s, const void* g) {
    asm volatile("cp.async.cg.shared.global [%0], [%1], 16;" :: "r"(s), "l"(g));
}
__device__ __forceinline__ void cpa_commit() {
    asm volatile("cp.async.commit_group;" ::: "memory");
}
template<int N> __device__ __forceinline__ void cpa_wait() {
    asm volatile("cp.async.wait_group %0;" :: "n"(N) : "memory");
}
__device__ __forceinline__ void ldsm_x4(uint32_t& r0, uint32_t& r1, uint32_t& r2, uint32_t& r3,
                                        uint32_t addr) {
    asm volatile("ldmatrix.sync.aligned.m8n8.x4.shared.b16 {%0,%1,%2,%3}, [%4];"
                 : "=r"(r0), "=r"(r1), "=r"(r2), "=r"(r3) : "r"(addr));
}
__device__ __forceinline__ void mma_f16(float& c0, float& c1, float& c2, float& c3,
                                        uint32_t a0, uint32_t a1, uint32_t a2, uint32_t a3,
                                        uint32_t b0, uint32_t b1) {
    asm volatile(
        "mma.sync.aligned.m16n8k16.row.col.f32.f16.f16.f32 "
        "{%0,%1,%2,%3}, {%4,%5,%6,%7}, {%8,%9}, {%0,%1,%2,%3};"
        : "+f"(c0), "+f"(c1), "+f"(c2), "+f"(c3)
        : "r"(a0), "r"(a1), "r"(a2), "r"(a3), "r"(b0), "r"(b1));
}
// f32x2
__device__ __forceinline__ u64t pack2(float lo, float hi) {
    u64t d; asm("mov.b64 %0, {%1, %2};" : "=l"(d) : "f"(lo), "f"(hi)); return d;
}
__device__ __forceinline__ u64t pack_dup(float x) {
    u64t d; asm("mov.b64 %0, {%1, %1};" : "=l"(d) : "f"(x)); return d;
}
__device__ __forceinline__ void unpack2(u64t v, float& lo, float& hi) {
    asm("mov.b64 {%0, %1}, %2;" : "=f"(lo), "=f"(hi) : "l"(v));
}
__device__ __forceinline__ u64t fma2(u64t a, u64t b, u64t c) {
    u64t d; asm("fma.rn.f32x2 %0, %1, %2, %3;" : "=l"(d) : "l"(a), "l"(b), "l"(c)); return d;
}
__device__ __forceinline__ u64t mul2(u64t a, u64t b) {
    u64t d; asm("mul.rn.f32x2 %0, %1, %2;" : "=l"(d) : "l"(a), "l"(b)); return d;
}

// ---------------------------------------------------------------- expand / convert
__global__ void expandA_kernel(const float* __restrict__ s, __half* __restrict__ d, int M) {
    int idx = blockIdx.x * blockDim.x + threadIdx.x;
    if (idx >= M * KDIM) return;
    int m = idx / KDIM, k = idx - m * KDIM;
    float x = s[idx];
    __half hi = __float2half(x);
    __half lo = __float2half(x - __half2float(hi));
    __half* row = d + (size_t)m * K2;
    row[k] = hi; row[KDIM + k] = lo;
}
// merged weight conversion: rows [0,2048)=Wq, [2048,2560)=Wk, [2560,3072)=Wv -> wh;
// rows [3072,5120)=Wo -> woh
__global__ void conv_w_kernel(const float* __restrict__ Wq, const float* __restrict__ Wk,
                              const float* __restrict__ Wv, const float* __restrict__ Wo,
                              __half* __restrict__ wh, __half* __restrict__ woh) {
    int idx = blockIdx.x * blockDim.x + threadIdx.x;
    if (idx >= (QKVDIM + HIDD) * KDIM) return;
    int r = idx >> 11;              // KDIM = 2048
    int k = idx & (KDIM - 1);
    float x;
    if (r < HIDD)                 x = Wq[(size_t)r * KDIM + k];
    else if (r < HIDD + KVDIM)    x = Wk[(size_t)(r - HIDD) * KDIM + k];
    else if (r < QKVDIM)          x = Wv[(size_t)(r - HIDD - KVDIM) * KDIM + k];
    else                          x = Wo[(size_t)(r - QKVDIM) * KDIM + k];
    if (r < QKVDIM) wh[idx] = __float2half(x);
    else            woh[(size_t)(r - QKVDIM) * KDIM + k] = __float2half(x);
}

// ---------------------------------------------------------------- fp16 HMMA GEMM
// C[M,N] = A'[M,K2] * B[N,KDIM]^T with B k-offset wrapped mod KDIM.
#define BK3   32
#define NK2   (K2 / BK3)         // 128
#define SROWB 80
#define ATILE_B (128 * SROWB)
#define STAGE_B (2 * ATILE_B)
#define GSMEM  (3 * STAGE_B)

__global__ __launch_bounds__(256, 2) void gemm_f16(
    const __half* __restrict__ A, const __half* __restrict__ B,
    float* __restrict__ C, int N)
{
    extern __shared__ __align__(128) char smem[];
    const uint32_t sb = smem_u32(smem);
    const int tid  = threadIdx.x;
    const int lane = tid & 31;
    const int wid  = tid >> 5;
    const int wm   = wid & 3;
    const int wn   = wid >> 2;
    const int bm = blockIdx.y * 128, bn = blockIdx.x * 128;

    const int lrow = tid >> 1;
    const int lc   = (tid & 1) * 2;
    const __half* Ab = A + (size_t)(bm + lrow) * K2 + lc * 8;
    const __half* Bb = B + (size_t)(bn + lrow) * KDIM + lc * 8;
    const uint32_t saA = sb + lrow * SROWB + lc * 16;
    const uint32_t saB = sb + ATILE_B + lrow * SROWB + lc * 16;

    float acc[2][8][4];
#pragma unroll
    for (int i = 0; i < 2; i++)
#pragma unroll
        for (int j = 0; j < 8; j++)
#pragma unroll
            for (int r = 0; r < 4; r++) acc[i][j][r] = 0.f;

    const int a_row = wm * 32 + (lane & 15);
    const int a_kb  = (lane >> 4) * 16;
    const int b_row = wn * 64 + ((lane >> 4) << 3) + (lane & 7);
    const int b_kb  = ((lane >> 3) & 1) * 16;

#pragma unroll
    for (int s = 0; s < 2; s++) {
        cpa16(saA + s * STAGE_B,      Ab + s * BK3);
        cpa16(saA + s * STAGE_B + 16, Ab + s * BK3 + 8);
        cpa16(saB + s * STAGE_B,      Bb + s * BK3);
        cpa16(saB + s * STAGE_B + 16, Bb + s * BK3 + 8);
        cpa_commit();
    }

    for (int kt = 0; kt < NK2; kt++) {
        cpa_wait<1>();
        __syncthreads();

        if (kt + 2 < NK2) {
            const int ps = (kt + 2) % 3;
            const int kA = (kt + 2) * BK3;
            const int kB = kA & (KDIM - 1);
            cpa16(saA + ps * STAGE_B,      Ab + kA);
            cpa16(saA + ps * STAGE_B + 16, Ab + kA + 8);
            cpa16(saB + ps * STAGE_B,      Bb + kB);
            cpa16(saB + ps * STAGE_B + 16, Bb + kB + 8);
        }
        cpa_commit();

        const uint32_t sAs = sb + (kt % 3) * STAGE_B;
        const uint32_t sBs = sAs + ATILE_B;

#pragma unroll
        for (int kh = 0; kh < 2; kh++) {
            const int kbyte = kh * 32;
            uint32_t a[2][4];
#pragma unroll
            for (int mt = 0; mt < 2; mt++)
                ldsm_x4(a[mt][0], a[mt][1], a[mt][2], a[mt][3],
                        sAs + (a_row + mt * 16) * SROWB + kbyte + a_kb);
            uint32_t b[4][4];
#pragma unroll
            for (int nt = 0; nt < 4; nt++)
                ldsm_x4(b[nt][0], b[nt][1], b[nt][2], b[nt][3],
                        sBs + (b_row + nt * 16) * SROWB + kbyte + b_kb);
#pragma unroll
            for (int mt = 0; mt < 2; mt++)
#pragma unroll
                for (int j = 0; j < 8; j++)
                    mma_f16(acc[mt][j][0], acc[mt][j][1], acc[mt][j][2], acc[mt][j][3],
                            a[mt][0], a[mt][1], a[mt][2], a[mt][3],
                            b[j >> 1][(j & 1) * 2], b[j >> 1][(j & 1) * 2 + 1]);
        }
        __syncthreads();
    }

#pragma unroll
    for (int mt = 0; mt < 2; mt++) {
        int m0 = bm + wm * 32 + mt * 16 + (lane >> 2);
#pragma unroll
        for (int j = 0; j < 8; j++) {
            int n0 = bn + wn * 64 + j * 8 + (lane & 3) * 2;
            float2 v0 = { acc[mt][j][0], acc[mt][j][1] };
            float2 v1 = { acc[mt][j][2], acc[mt][j][3] };
            *(float2*)(C + (size_t)m0 * N + n0)       = v0;
            *(float2*)(C + (size_t)(m0 + 8) * N + n0) = v1;
        }
    }
}

// ---------------------------------------------------------------- attention
// Fused: RoPE on Q (registers) + RoPE on K (during tile fill) + hi/lo fp16
// epilogue into g_at_e. LPT: heaviest q-tiles scheduled first.
#define AQ 128
#define AK 32
#define KPAD 68

__global__ __launch_bounds__(128) void attn_kernel(
    const float* __restrict__ QKV, const float* __restrict__ cs,
    const float* __restrict__ sn, __half* __restrict__ ATE)
{
    __shared__ float Ks[AK][KPAD];
    __shared__ float Vs[AK][KPAD];

    const int tid = threadIdx.x;
    const int b   = blockIdx.y >> 5;
    const int h   = blockIdx.y & 31;
    const int kvh = h >> 2;
    const int qt  = gridDim.x - 1 - blockIdx.x;   // heavy tiles first
    const int qrow = qt * AQ + tid;

    const float scale = 0.125f;
    const float* qp  = QKV + (size_t)(b * SS + qrow) * QKVDIM + h * DH;
    const float* csq = cs + (size_t)(b * SS + qrow) * DH;
    const float* snq = sn + (size_t)(b * SS + qrow) * DH;

    // load Q, apply RoPE in registers, scale, pack
    float x[DH];
#pragma unroll
    for (int i = 0; i < DH / 4; i++) {
        float4 v = *(const float4*)(qp + 4 * i);
        x[4*i] = v.x; x[4*i+1] = v.y; x[4*i+2] = v.z; x[4*i+3] = v.w;
    }
    u64t q2[DH / 2], o2[DH / 2];
#pragma unroll
    for (int d = 0; d < 32; d += 2) {
        float c0 = csq[d], c1 = csq[d + 1];
        float s0 = snq[d], s1 = snq[d + 1];
        float lo0 = (x[d]      * c0 - x[d + 32] * s0) * scale;
        float lo1 = (x[d + 1]  * c1 - x[d + 33] * s1) * scale;
        float hi0 = (x[d + 32] * c0 + x[d]      * s0) * scale;
        float hi1 = (x[d + 33] * c1 + x[d + 1]  * s1) * scale;
        q2[d / 2]      = pack2(lo0, lo1);
        q2[d / 2 + 16] = pack2(hi0, hi1);
    }
#pragma unroll
    for (int d = 0; d < DH / 2; d++) o2[d] = pack2(0.f, 0.f);

    float m = -1e30f, l = 0.f;
    const int nt = (qt * AQ + AQ) / AK;

    const int lj   = tid >> 2;          // K/V row within tile
    const int loff = (tid & 3) << 2;    // 0,4,8,12

    for (int t = 0; t < nt; t++) {
        const int k0 = t * AK;
        __syncthreads();
        {
            const int krow = b * SS + k0 + lj;
            const float* kp = QKV + (size_t)krow * QKVDIM + HIDD + kvh * DH;
            const float* vp = kp + KVDIM;
            float4 k0v = *(const float4*)(kp + loff);
            float4 k1v = *(const float4*)(kp + loff + 16);
            float4 k2v = *(const float4*)(kp + loff + 32);
            float4 k3v = *(const float4*)(kp + loff + 48);
            float4 c0v = *(const float4*)(cs + (size_t)krow * DH + loff);
            float4 c1v = *(const float4*)(cs + (size_t)krow * DH + loff + 16);
            float4 s0v = *(const float4*)(sn + (size_t)krow * DH + loff);
            float4 s1v = *(const float4*)(sn + (size_t)krow * DH + loff + 16);
            float4 r;
            r = make_float4(k0v.x*c0v.x - k2v.x*s0v.x, k0v.y*c0v.y - k2v.y*s0v.y,
                            k0v.z*c0v.z - k2v.z*s0v.z, k0v.w*c0v.w - k2v.w*s0v.w);
            *(float4*)&Ks[lj][loff] = r;
            r = make_float4(k2v.x*c0v.x + k0v.x*s0v.x, k2v.y*c0v.y + k0v.y*s0v.y,
                            k2v.z*c0v.z + k0v.z*s0v.z, k2v.w*c0v.w + k0v.w*s0v.w);
            *(float4*)&Ks[lj][loff + 32] = r;
            r = make_float4(k1v.x*c1v.x - k3v.x*s1v.x, k1v.y*c1v.y - k3v.y*s1v.y,
                            k1v.z*c1v.z - k3v.z*s1v.z, k1v.w*c1v.w - k3v.w*s1v.w);
            *(float4*)&Ks[lj][loff + 16] = r;
            r = make_float4(k3v.x*c1v.x + k1v.x*s1v.x, k3v.y*c1v.y + k1v.y*s1v.y,
                            k3v.z*c1v.z + k1v.z*s1v.z, k3v.w*c1v.w + k1v.w*s1v.w);
            *(float4*)&Ks[lj][loff + 48] = r;
#pragma unroll
            for (int i = 0; i < 4; i++) {
                int c = loff + 16 * i;
                *(float4*)&Vs[lj][c] = *(const float4*)(vp + c);
            }
        }
        __syncthreads();

        float s[AK];
        float tmax = -1e30f;
#pragma unroll
        for (int j = 0; j < AK; j++) {
            u64t acc = pack2(0.f, 0.f);
#pragma unroll
            for (int d = 0; d < DH / 4; d++) {
                ulonglong2 kk2 = *(const ulonglong2*)&Ks[j][4 * d];
                acc = fma2(q2[2 * d + 0], kk2.x, acc);
                acc = fma2(q2[2 * d + 1], kk2.y, acc);
            }
            float alo, ahi;
            unpack2(acc, alo, ahi);
            float sc = alo + ahi;
            sc = (k0 + j <= qrow) ? sc : -1e30f;
            s[j] = sc;
            tmax = fmaxf(tmax, sc);
        }

        if (tmax > m) {
            float mn = tmax;
            float corr = __expf(m - mn);
            m = mn;
            l *= corr;
            u64t cd = pack_dup(corr);
#pragma unroll
            for (int d = 0; d < DH / 2; d++) o2[d] = mul2(o2[d], cd);
        }

#pragma unroll
        for (int j = 0; j < AK; j++) {
            float p = __expf(s[j] - m);
            l += p;
            u64t pd = pack_dup(p);
#pragma unroll
            for (int d = 0; d < DH / 4; d++) {
                ulonglong2 v2 = *(const ulonglong2*)&Vs[j][4 * d];
                o2[2 * d + 0] = fma2(pd, v2.x, o2[2 * d + 0]);
                o2[2 * d + 1] = fma2(pd, v2.y, o2[2 * d + 1]);
            }
        }
    }

    // epilogue: normalize, split to fp16 hi/lo, write to g_at_e layout
    const float inv = 1.f / l;
    __half* orow = ATE + (size_t)(b * SS + qrow) * K2 + h * DH;
    __half hbuf[DH], lbuf[DH];
#pragma unroll
    for (int d = 0; d < DH / 2; d++) {
        float v0, v1;
        unpack2(o2[d], v0, v1);
        v0 *= inv; v1 *= inv;
        __half h0 = __float2half(v0);
        __half h1 = __float2half(v1);
        hbuf[2*d]   = h0;
        hbuf[2*d+1] = h1;
        lbuf[2*d]   = __float2half(v0 - __half2float(h0));
        lbuf[2*d+1] = __float2half(v1 - __half2float(h1));
    }
#pragma unroll
    for (int c = 0; c < DH; c += 8) {
        *(uint4*)(orow + c)        = *(const uint4*)(hbuf + c);
        *(uint4*)(orow + KDIM + c) = *(const uint4*)(lbuf + c);
    }
}

// ---------------------------------------------------------------- launch
extern "C" void kernel_launch(void* const* d_in, const int* in_sizes, int n_in,
                              void* d_out, int out_size)
{
    const float* hs = (const float*)d_in[0];
    const float* cs = (const float*)d_in[1];
    const float* sn = (const float*)d_in[2];
    const float* Wq = (const float*)d_in[4];
    const float* Wk = (const float*)d_in[5];
    const float* Wv = (const float*)d_in[6];
    const float* Wo = (const float*)d_in[7];
    float* out = (float*)d_out;

    float* qkv;
    cudaGetSymbolAddress((void**)&qkv, g_qkv);
    __half *hse, *wh, *woh, *ate;
    cudaGetSymbolAddress((void**)&hse, g_hs_e);
    cudaGetSymbolAddress((void**)&wh,  g_w_h);
    cudaGetSymbolAddress((void**)&woh, g_wo_h);
    cudaGetSymbolAddress((void**)&ate, g_at_e);

    cudaFuncSetAttribute(gemm_f16, cudaFuncAttributeMaxDynamicSharedMemorySize, GSMEM);

    const int nHS = MROWS * KDIM;
    const int nW  = (QKVDIM + HIDD) * KDIM;
    expandA_kernel<<<(nHS + 255) / 256, 256>>>(hs, hse, MROWS);
    conv_w_kernel<<<(nW + 255) / 256, 256>>>(Wq, Wk, Wv, Wo, wh, woh);

    // merged QKV projection
    gemm_f16<<<dim3(QKVDIM / 128, MROWS / 128), 256, GSMEM>>>(hse, wh, qkv, QKVDIM);

    // fused rope + attention + hi/lo split epilogue
    attn_kernel<<<dim3(SS / AQ, BB * NH), dim3(128)>>>(qkv, cs, sn, ate);

    // output projection
    gemm_f16<<<dim3(HIDD / 128, MROWS / 128), 256, GSMEM>>>(ate, woh, out, HIDD);
}

// round 12
// speedup vs baseline: 1.8500x; 1.0146x over previous
#include <cuda_runtime.h>
#include <cuda_fp16.h>
#include <cstdint>
#include <math.h>

// ---------------------------------------------------------------- constants
#define BB   2
#define SS   2048
#define HIDD 2048
#define NH   32
#define NKV  8
#define DH   64
#define MROWS (BB*SS)        // 4096
#define KVDIM (NKV*DH)       // 512
#define KDIM  2048
#define K2   (2*KDIM)        // 4096: A expanded as [hi | lo]
#define QKVDIM (HIDD + 2*KVDIM)   // 3072

typedef unsigned long long u64t;

// ---------------------------------------------------------------- scratch
__device__ float g_qkv[(size_t)MROWS * QKVDIM];   // 48 MB
__device__ __half g_hs_e[(size_t)MROWS * K2];     // 32 MB [hi|lo]
__device__ __half g_w_h [(size_t)QKVDIM * KDIM];  // 12 MB fp16(W) merged q|k|v
__device__ __half g_wo_h[(size_t)HIDD  * KDIM];   //  8 MB
__device__ __half g_at_e[(size_t)MROWS * K2];     // 32 MB [hi|lo]

// ---------------------------------------------------------------- helpers
__device__ __forceinline__ uint32_t smem_u32(const void* p) {
    uint32_t a;
    asm("{ .reg .u64 t; cvta.to.shared.u64 t, %1; cvt.u32.u64 %0, t; }" : "=r"(a) : "l"(p));
    return a;
}
__device__ __forceinline__ void cpa16(uint32_t s, const void* g) {
    asm volatile("cp.async.cg.shared.global [%0], [%1], 16;" :: "r"(s), "l"(g));
}
__device__ __forceinline__ void cpa_commit() {
    asm volatile("cp.async.commit_group;" ::: "memory");
}
template<int N> __device__ __forceinline__ void cpa_wait() {
    asm volatile("cp.async.wait_group %0;" :: "n"(N) : "memory");
}
__device__ __forceinline__ void ldsm_x4(uint32_t& r0, uint32_t& r1, uint32_t& r2, uint32_t& r3,
                                        uint32_t addr) {
    asm volatile("ldmatrix.sync.aligned.m8n8.x4.shared.b16 {%0,%1,%2,%3}, [%4];"
                 : "=r"(r0), "=r"(r1), "=r"(r2), "=r"(r3) : "r"(addr));
}
__device__ __forceinline__ void mma_f16(float& c0, float& c1, float& c2, float& c3,
                                        uint32_t a0, uint32_t a1, uint32_t a2, uint32_t a3,
                                        uint32_t b0, uint32_t b1) {
    asm volatile(
        "mma.sync.aligned.m16n8k16.row.col.f32.f16.f16.f32 "
        "{%0,%1,%2,%3}, {%4,%5,%6,%7}, {%8,%9}, {%0,%1,%2,%3};"
        : "+f"(c0), "+f"(c1), "+f"(c2), "+f"(c3)
        : "r"(a0), "r"(a1), "r"(a2), "r"(a3), "r"(b0), "r"(b1));
}
// f32x2
__device__ __forceinline__ u64t pack2(float lo, float hi) {
    u64t d; asm("mov.b64 %0, {%1, %2};" : "=l"(d) : "f"(lo), "f"(hi)); return d;
}
__device__ __forceinline__ u64t pack_dup(float x) {
    u64t d; asm("mov.b64 %0, {%1, %1};" : "=l"(d) : "f"(x)); return d;
}
__device__ __forceinline__ void unpack2(u64t v, float& lo, float& hi) {
    asm("mov.b64 {%0, %1}, %2;" : "=f"(lo), "=f"(hi) : "l"(v));
}
__device__ __forceinline__ u64t fma2(u64t a, u64t b, u64t c) {
    u64t d; asm("fma.rn.f32x2 %0, %1, %2, %3;" : "=l"(d) : "l"(a), "l"(b), "l"(c)); return d;
}
__device__ __forceinline__ u64t mul2(u64t a, u64t b) {
    u64t d; asm("mul.rn.f32x2 %0, %1, %2;" : "=l"(d) : "l"(a), "l"(b)); return d;
}

// ---------------------------------------------------------------- expand / convert
__global__ void expandA_kernel(const float* __restrict__ s, __half* __restrict__ d, int M) {
    int idx = blockIdx.x * blockDim.x + threadIdx.x;
    if (idx >= M * KDIM) return;
    int m = idx / KDIM, k = idx - m * KDIM;
    float x = s[idx];
    __half hi = __float2half(x);
    __half lo = __float2half(x - __half2float(hi));
    __half* row = d + (size_t)m * K2;
    row[k] = hi; row[KDIM + k] = lo;
}
__global__ void conv_w_kernel(const float* __restrict__ Wq, const float* __restrict__ Wk,
                              const float* __restrict__ Wv, const float* __restrict__ Wo,
                              __half* __restrict__ wh, __half* __restrict__ woh) {
    int idx = blockIdx.x * blockDim.x + threadIdx.x;
    if (idx >= (QKVDIM + HIDD) * KDIM) return;
    int r = idx >> 11;
    int k = idx & (KDIM - 1);
    float x;
    if (r < HIDD)                 x = Wq[(size_t)r * KDIM + k];
    else if (r < HIDD + KVDIM)    x = Wk[(size_t)(r - HIDD) * KDIM + k];
    else if (r < QKVDIM)          x = Wv[(size_t)(r - HIDD - KVDIM) * KDIM + k];
    else                          x = Wo[(size_t)(r - QKVDIM) * KDIM + k];
    if (r < QKVDIM) wh[idx] = __float2half(x);
    else            woh[(size_t)(r - QKVDIM) * KDIM + k] = __float2half(x);
}

// ---------------------------------------------------------------- fp16 HMMA GEMM (R11 exact)
#define BK3   32
#define NK2   (K2 / BK3)         // 128
#define SROWB 80
#define ATILE_B (128 * SROWB)
#define STAGE_B (2 * ATILE_B)
#define GSMEM  (3 * STAGE_B)

__global__ __launch_bounds__(256, 2) void gemm_f16(
    const __half* __restrict__ A, const __half* __restrict__ B,
    float* __restrict__ C, int N)
{
    extern __shared__ __align__(128) char smem[];
    const uint32_t sb = smem_u32(smem);
    const int tid  = threadIdx.x;
    const int lane = tid & 31;
    const int wid  = tid >> 5;
    const int wm   = wid & 3;
    const int wn   = wid >> 2;
    const int bm = blockIdx.y * 128, bn = blockIdx.x * 128;

    const int lrow = tid >> 1;
    const int lc   = (tid & 1) * 2;
    const __half* Ab = A + (size_t)(bm + lrow) * K2 + lc * 8;
    const __half* Bb = B + (size_t)(bn + lrow) * KDIM + lc * 8;
    const uint32_t saA = sb + lrow * SROWB + lc * 16;
    const uint32_t saB = sb + ATILE_B + lrow * SROWB + lc * 16;

    float acc[2][8][4];
#pragma unroll
    for (int i = 0; i < 2; i++)
#pragma unroll
        for (int j = 0; j < 8; j++)
#pragma unroll
            for (int r = 0; r < 4; r++) acc[i][j][r] = 0.f;

    const int a_row = wm * 32 + (lane & 15);
    const int a_kb  = (lane >> 4) * 16;
    const int b_row = wn * 64 + ((lane >> 4) << 3) + (lane & 7);
    const int b_kb  = ((lane >> 3) & 1) * 16;

#pragma unroll
    for (int s = 0; s < 2; s++) {
        cpa16(saA + s * STAGE_B,      Ab + s * BK3);
        cpa16(saA + s * STAGE_B + 16, Ab + s * BK3 + 8);
        cpa16(saB + s * STAGE_B,      Bb + s * BK3);
        cpa16(saB + s * STAGE_B + 16, Bb + s * BK3 + 8);
        cpa_commit();
    }

    for (int kt = 0; kt < NK2; kt++) {
        cpa_wait<1>();
        __syncthreads();

        if (kt + 2 < NK2) {
            const int ps = (kt + 2) % 3;
            const int kA = (kt + 2) * BK3;
            const int kB = kA & (KDIM - 1);
            cpa16(saA + ps * STAGE_B,      Ab + kA);
            cpa16(saA + ps * STAGE_B + 16, Ab + kA + 8);
            cpa16(saB + ps * STAGE_B,      Bb + kB);
            cpa16(saB + ps * STAGE_B + 16, Bb + kB + 8);
        }
        cpa_commit();

        const uint32_t sAs = sb + (kt % 3) * STAGE_B;
        const uint32_t sBs = sAs + ATILE_B;

#pragma unroll
        for (int kh = 0; kh < 2; kh++) {
            const int kbyte = kh * 32;
            uint32_t a[2][4];
#pragma unroll
            for (int mt = 0; mt < 2; mt++)
                ldsm_x4(a[mt][0], a[mt][1], a[mt][2], a[mt][3],
                        sAs + (a_row + mt * 16) * SROWB + kbyte + a_kb);
            uint32_t b[4][4];
#pragma unroll
            for (int nt = 0; nt < 4; nt++)
                ldsm_x4(b[nt][0], b[nt][1], b[nt][2], b[nt][3],
                        sBs + (b_row + nt * 16) * SROWB + kbyte + b_kb);
#pragma unroll
            for (int mt = 0; mt < 2; mt++)
#pragma unroll
                for (int j = 0; j < 8; j++)
                    mma_f16(acc[mt][j][0], acc[mt][j][1], acc[mt][j][2], acc[mt][j][3],
                            a[mt][0], a[mt][1], a[mt][2], a[mt][3],
                            b[j >> 1][(j & 1) * 2], b[j >> 1][(j & 1) * 2 + 1]);
        }
        __syncthreads();
    }

#pragma unroll
    for (int mt = 0; mt < 2; mt++) {
        int m0 = bm + wm * 32 + mt * 16 + (lane >> 2);
#pragma unroll
        for (int j = 0; j < 8; j++) {
            int n0 = bn + wn * 64 + j * 8 + (lane & 3) * 2;
            float2 v0 = { acc[mt][j][0], acc[mt][j][1] };
            float2 v1 = { acc[mt][j][2], acc[mt][j][3] };
            *(float2*)(C + (size_t)m0 * N + n0)       = v0;
            *(float2*)(C + (size_t)(m0 + 8) * N + n0) = v1;
        }
    }
}

// ---------------------------------------------------------------- RoPE on K region only (once)
__global__ void ropeK_kernel(float* __restrict__ qkv,
                             const float* __restrict__ cs, const float* __restrict__ sn)
{
    int idx = blockIdx.x * blockDim.x + threadIdx.x;   // MROWS*NKV*32
    int d = idx & 31;
    int h = (idx >> 5) & (NKV - 1);
    int r = idx >> 8;
    float c = cs[r * DH + d], s = sn[r * DH + d];
    float* p = qkv + (size_t)r * QKVDIM + HIDD + h * DH + d;
    float x1 = p[0], x2 = p[32];
    p[0]  = x1 * c - x2 * s;
    p[32] = x2 * c + x1 * s;
}

// ---------------------------------------------------------------- attention
// Q-RoPE fused (registers), K pre-roped, cp.async double-buffered K/V tiles,
// hi/lo fp16 epilogue into g_at_e. LPT: heaviest q-tiles first.
#define AQ 128
#define AK 32
#define KPAD 68
#define KPADB (KPAD * 4)                        // 272 B per row
#define ABUF_B (AK * KPADB)                     // one K or V buffer: 8704 B
#define ASMEM (4 * ABUF_B)                      // K0 K1 V0 V1 = 34816 B

__global__ __launch_bounds__(128) void attn_kernel(
    const float* __restrict__ QKV, const float* __restrict__ cs,
    const float* __restrict__ sn, __half* __restrict__ ATE)
{
    extern __shared__ __align__(16) float asmem[];
    const uint32_t sKb = smem_u32(asmem);            // K buffers [2][AK][KPAD]
    const uint32_t sVb = sKb + 2 * ABUF_B;           // V buffers [2][AK][KPAD]
    const float* KsF = asmem;
    const float* VsF = asmem + 2 * AK * KPAD;

    const int tid = threadIdx.x;
    const int b   = blockIdx.y >> 5;
    const int h   = blockIdx.y & 31;
    const int kvh = h >> 2;
    const int qt  = gridDim.x - 1 - blockIdx.x;      // heavy tiles first
    const int qrow = qt * AQ + tid;

    const float scale = 0.125f;
    const float* qp  = QKV + (size_t)(b * SS + qrow) * QKVDIM + h * DH;
    const float* csq = cs + (size_t)(b * SS + qrow) * DH;
    const float* snq = sn + (size_t)(b * SS + qrow) * DH;

    // Q: load + RoPE + scale + pack, 4 pairs at a time (small temps)
    u64t q2[DH / 2], o2[DH / 2];
#pragma unroll
    for (int d0 = 0; d0 < 32; d0 += 4) {
        float4 va = *(const float4*)(qp + d0);
        float4 vb = *(const float4*)(qp + d0 + 32);
        float4 cv = *(const float4*)(csq + d0);
        float4 sv = *(const float4*)(snq + d0);
        q2[d0 / 2]      = pack2((va.x*cv.x - vb.x*sv.x)*scale, (va.y*cv.y - vb.y*sv.y)*scale);
        q2[d0 / 2 + 1]  = pack2((va.z*cv.z - vb.z*sv.z)*scale, (va.w*cv.w - vb.w*sv.w)*scale);
        q2[d0 / 2 + 16] = pack2((vb.x*cv.x + va.x*sv.x)*scale, (vb.y*cv.y + va.y*sv.y)*scale);
        q2[d0 / 2 + 17] = pack2((vb.z*cv.z + va.z*sv.z)*scale, (vb.w*cv.w + va.w*sv.w)*scale);
    }
#pragma unroll
    for (int d = 0; d < DH / 2; d++) o2[d] = pack2(0.f, 0.f);

    float m = -1e30f, l = 0.f;
    const int nt = qt + 1;                 // tiles of AK=32: (qt*128+128)/32 ... = 4*(qt+1)
    const int ntiles = 4 * nt;

    const int lj   = tid >> 2;             // K/V row within tile
    const int loff = (tid & 3) << 2;       // 0,4,8,12
    const float* kbase = QKV + (size_t)(b * SS + lj) * QKVDIM + HIDD + kvh * DH;

    // prefetch tiles 0,1
#pragma unroll
    for (int p = 0; p < 2; p++) {
        if (p < ntiles) {
            const float* kp = kbase + (size_t)p * AK * QKVDIM;
            const uint32_t kd = sKb + p * ABUF_B + lj * KPADB + (loff << 2);
            const uint32_t vd = sVb + p * ABUF_B + lj * KPADB + (loff << 2);
            cpa16(kd,       kp + loff);          cpa16(vd,       kp + KVDIM + loff);
            cpa16(kd + 64,  kp + loff + 16);     cpa16(vd + 64,  kp + KVDIM + loff + 16);
            cpa16(kd + 128, kp + loff + 32);     cpa16(vd + 128, kp + KVDIM + loff + 32);
            cpa16(kd + 192, kp + loff + 48);     cpa16(vd + 192, kp + KVDIM + loff + 48);
        }
        cpa_commit();
    }

    for (int t = 0; t < ntiles; t++) {
        cpa_wait<1>();
        __syncthreads();
        const int buf = t & 1;
        const int k0 = t * AK;
        const float* Kt = KsF + buf * AK * KPAD;
        const float* Vt = VsF + buf * AK * KPAD;

        float s[AK];
        float tmax = -1e30f;
#pragma unroll
        for (int j = 0; j < AK; j++) {
            u64t acc = pack2(0.f, 0.f);
#pragma unroll
            for (int d = 0; d < DH / 4; d++) {
                ulonglong2 kk2 = *(const ulonglong2*)&Kt[j * KPAD + 4 * d];
                acc = fma2(q2[2 * d + 0], kk2.x, acc);
                acc = fma2(q2[2 * d + 1], kk2.y, acc);
            }
            float alo, ahi;
            unpack2(acc, alo, ahi);
            float sc = alo + ahi;
            sc = (k0 + j <= qrow) ? sc : -1e30f;
            s[j] = sc;
            tmax = fmaxf(tmax, sc);
        }

        if (tmax > m) {
            float mn = tmax;
            float corr = __expf(m - mn);
            m = mn;
            l *= corr;
            u64t cd = pack_dup(corr);
#pragma unroll
            for (int d = 0; d < DH / 2; d++) o2[d] = mul2(o2[d], cd);
        }

#pragma unroll
        for (int j = 0; j < AK; j++) {
            float p = __expf(s[j] - m);
            l += p;
            u64t pd = pack_dup(p);
#pragma unroll
            for (int d = 0; d < DH / 4; d++) {
                ulonglong2 v2 = *(const ulonglong2*)&Vt[j * KPAD + 4 * d];
                o2[2 * d + 0] = fma2(pd, v2.x, o2[2 * d + 0]);
                o2[2 * d + 1] = fma2(pd, v2.y, o2[2 * d + 1]);
            }
        }

        __syncthreads();   // all threads done with buf before overwrite
        if (t + 2 < ntiles) {
            const float* kp = kbase + (size_t)(t + 2) * AK * QKVDIM;
            const uint32_t kd = sKb + buf * ABUF_B + lj * KPADB + (loff << 2);
            const uint32_t vd = sVb + buf * ABUF_B + lj * KPADB + (loff << 2);
            cpa16(kd,       kp + loff);          cpa16(vd,       kp + KVDIM + loff);
            cpa16(kd + 64,  kp + loff + 16);     cpa16(vd + 64,  kp + KVDIM + loff + 16);
            cpa16(kd + 128, kp + loff + 32);     cpa16(vd + 128, kp + KVDIM + loff + 32);
            cpa16(kd + 192, kp + loff + 48);     cpa16(vd + 192, kp + KVDIM + loff + 48);
        }
        cpa_commit();
    }

    // epilogue: normalize, hi/lo fp16 split, small staging window
    const float inv = 1.f / l;
    __half* orow = ATE + (size_t)(b * SS + qrow) * K2 + h * DH;
#pragma unroll
    for (int c = 0; c < DH; c += 8) {
        __half hb[8], lb[8];
#pragma unroll
        for (int e = 0; e < 8; e += 2) {
            float v0, v1;
            unpack2(o2[(c + e) / 2], v0, v1);
            v0 *= inv; v1 *= inv;
            __half h0 = __float2half(v0);
            __half h1 = __float2half(v1);
            hb[e] = h0; hb[e + 1] = h1;
            lb[e] = __float2half(v0 - __half2float(h0));
            lb[e + 1] = __float2half(v1 - __half2float(h1));
        }
        *(uint4*)(orow + c)        = *(const uint4*)hb;
        *(uint4*)(orow + KDIM + c) = *(const uint4*)lb;
    }
}

// ---------------------------------------------------------------- launch
extern "C" void kernel_launch(void* const* d_in, const int* in_sizes, int n_in,
                              void* d_out, int out_size)
{
    const float* hs = (const float*)d_in[0];
    const float* cs = (const float*)d_in[1];
    const float* sn = (const float*)d_in[2];
    const float* Wq = (const float*)d_in[4];
    const float* Wk = (const float*)d_in[5];
    const float* Wv = (const float*)d_in[6];
    const float* Wo = (const float*)d_in[7];
    float* out = (float*)d_out;

    float* qkv;
    cudaGetSymbolAddress((void**)&qkv, g_qkv);
    __half *hse, *wh, *woh, *ate;
    cudaGetSymbolAddress((void**)&hse, g_hs_e);
    cudaGetSymbolAddress((void**)&wh,  g_w_h);
    cudaGetSymbolAddress((void**)&woh, g_wo_h);
    cudaGetSymbolAddress((void**)&ate, g_at_e);

    cudaFuncSetAttribute(gemm_f16, cudaFuncAttributeMaxDynamicSharedMemorySize, GSMEM);
    cudaFuncSetAttribute(attn_kernel, cudaFuncAttributeMaxDynamicSharedMemorySize, ASMEM);

    const int nHS = MROWS * KDIM;
    const int nW  = (QKVDIM + HIDD) * KDIM;
    expandA_kernel<<<(nHS + 255) / 256, 256>>>(hs, hse, MROWS);
    conv_w_kernel<<<(nW + 255) / 256, 256>>>(Wq, Wk, Wv, Wo, wh, woh);

    // merged QKV projection
    gemm_f16<<<dim3(QKVDIM / 128, MROWS / 128), 256, GSMEM>>>(hse, wh, qkv, QKVDIM);

    // K-RoPE (once), then fused attention
    const int kpairs = MROWS * NKV * (DH / 2);
    ropeK_kernel<<<kpairs / 256, 256>>>(qkv, cs, sn);
    attn_kernel<<<dim3(SS / AQ, BB * NH), dim3(128), ASMEM>>>(qkv, cs, sn, ate);

    // output projection
    gemm_f16<<<dim3(HIDD / 128, MROWS / 128), 256, GSMEM>>>(ate, woh, out, HIDD);
}

// round 13
// speedup vs baseline: 2.1817x; 1.1793x over previous
#include <cuda_runtime.h>
#include <cuda_fp16.h>
#include <cstdint>
#include <math.h>

// ---------------------------------------------------------------- constants
#define BB   2
#define SS   2048
#define HIDD 2048
#define NH   32
#define NKV  8
#define DH   64
#define MROWS (BB*SS)        // 4096
#define KVDIM (NKV*DH)       // 512
#define KDIM  2048
#define QKVDIM (HIDD + 2*KVDIM)   // 3072

typedef unsigned long long u64t;

// ---------------------------------------------------------------- scratch
__device__ float g_qkv[(size_t)MROWS * QKVDIM];   // 48 MB
__device__ __half g_hs_h[(size_t)MROWS * KDIM];   // 16 MB fp16(hs)
__device__ __half g_w_h [(size_t)QKVDIM * KDIM];  // 12 MB fp16(W) merged q|k|v
__device__ __half g_wo_h[(size_t)HIDD  * KDIM];   //  8 MB
__device__ __half g_at_h[(size_t)MROWS * KDIM];   // 16 MB fp16(attn out)

// ---------------------------------------------------------------- helpers
__device__ __forceinline__ uint32_t smem_u32(const void* p) {
    uint32_t a;
    asm("{ .reg .u64 t; cvta.to.shared.u64 t, %1; cvt.u32.u64 %0, t; }" : "=r"(a) : "l"(p));
    return a;
}
__device__ __forceinline__ void cpa16(uint32_t s, const void* g) {
    asm volatile("cp.async.cg.shared.global [%0], [%1], 16;" :: "r"(s), "l"(g));
}
__device__ __forceinline__ void cpa_commit() {
    asm volatile("cp.async.commit_group;" ::: "memory");
}
template<int N> __device__ __forceinline__ void cpa_wait() {
    asm volatile("cp.async.wait_group %0;" :: "n"(N) : "memory");
}
__device__ __forceinline__ void ldsm_x4(uint32_t& r0, uint32_t& r1, uint32_t& r2, uint32_t& r3,
                                        uint32_t addr) {
    asm volatile("ldmatrix.sync.aligned.m8n8.x4.shared.b16 {%0,%1,%2,%3}, [%4];"
                 : "=r"(r0), "=r"(r1), "=r"(r2), "=r"(r3) : "r"(addr));
}
__device__ __forceinline__ void mma_f16(float& c0, float& c1, float& c2, float& c3,
                                        uint32_t a0, uint32_t a1, uint32_t a2, uint32_t a3,
                                        uint32_t b0, uint32_t b1) {
    asm volatile(
        "mma.sync.aligned.m16n8k16.row.col.f32.f16.f16.f32 "
        "{%0,%1,%2,%3}, {%4,%5,%6,%7}, {%8,%9}, {%0,%1,%2,%3};"
        : "+f"(c0), "+f"(c1), "+f"(c2), "+f"(c3)
        : "r"(a0), "r"(a1), "r"(a2), "r"(a3), "r"(b0), "r"(b1));
}
// f32x2
__device__ __forceinline__ u64t pack2(float lo, float hi) {
    u64t d; asm("mov.b64 %0, {%1, %2};" : "=l"(d) : "f"(lo), "f"(hi)); return d;
}
__device__ __forceinline__ u64t pack_dup(float x) {
    u64t d; asm("mov.b64 %0, {%1, %1};" : "=l"(d) : "f"(x)); return d;
}
__device__ __forceinline__ void unpack2(u64t v, float& lo, float& hi) {
    asm("mov.b64 {%0, %1}, %2;" : "=f"(lo), "=f"(hi) : "l"(v));
}
__device__ __forceinline__ u64t fma2(u64t a, u64t b, u64t c) {
    u64t d; asm("fma.rn.f32x2 %0, %1, %2, %3;" : "=l"(d) : "l"(a), "l"(b), "l"(c)); return d;
}
__device__ __forceinline__ u64t mul2(u64t a, u64t b) {
    u64t d; asm("mul.rn.f32x2 %0, %1, %2;" : "=l"(d) : "l"(a), "l"(b)); return d;
}

// ---------------------------------------------------------------- converts
__global__ void conv_kernel(const float* __restrict__ s, __half* __restrict__ d, int n) {
    int idx = blockIdx.x * blockDim.x + threadIdx.x;
    if (idx < n) d[idx] = __float2half(s[idx]);
}
__global__ void conv_w_kernel(const float* __restrict__ Wq, const float* __restrict__ Wk,
                              const float* __restrict__ Wv, const float* __restrict__ Wo,
                              __half* __restrict__ wh, __half* __restrict__ woh) {
    int idx = blockIdx.x * blockDim.x + threadIdx.x;
    if (idx >= (QKVDIM + HIDD) * KDIM) return;
    int r = idx >> 11;
    int k = idx & (KDIM - 1);
    float x;
    if (r < HIDD)                 x = Wq[(size_t)r * KDIM + k];
    else if (r < HIDD + KVDIM)    x = Wk[(size_t)(r - HIDD) * KDIM + k];
    else if (r < QKVDIM)          x = Wv[(size_t)(r - HIDD - KVDIM) * KDIM + k];
    else                          x = Wo[(size_t)(r - QKVDIM) * KDIM + k];
    if (r < QKVDIM) wh[idx] = __float2half(x);
    else            woh[(size_t)(r - QKVDIM) * KDIM + k] = __float2half(x);
}

// ---------------------------------------------------------------- fp16 HMMA GEMM (single pass)
// C[M,N] = A[M,KDIM] * B[N,KDIM]^T
#define BK3   32
#define NKIT  (KDIM / BK3)       // 64
#define SROWB 80
#define ATILE_B (128 * SROWB)
#define STAGE_B (2 * ATILE_B)
#define GSMEM  (3 * STAGE_B)

__global__ __launch_bounds__(256, 2) void gemm_f16(
    const __half* __restrict__ A, const __half* __restrict__ B,
    float* __restrict__ C, int N)
{
    extern __shared__ __align__(128) char smem[];
    const uint32_t sb = smem_u32(smem);
    const int tid  = threadIdx.x;
    const int lane = tid & 31;
    const int wid  = tid >> 5;
    const int wm   = wid & 3;
    const int wn   = wid >> 2;
    const int bm = blockIdx.y * 128, bn = blockIdx.x * 128;

    const int lrow = tid >> 1;
    const int lc   = (tid & 1) * 2;
    const __half* Ab = A + (size_t)(bm + lrow) * KDIM + lc * 8;
    const __half* Bb = B + (size_t)(bn + lrow) * KDIM + lc * 8;
    const uint32_t saA = sb + lrow * SROWB + lc * 16;
    const uint32_t saB = sb + ATILE_B + lrow * SROWB + lc * 16;

    float acc[2][8][4];
#pragma unroll
    for (int i = 0; i < 2; i++)
#pragma unroll
        for (int j = 0; j < 8; j++)
#pragma unroll
            for (int r = 0; r < 4; r++) acc[i][j][r] = 0.f;

    const int a_row = wm * 32 + (lane & 15);
    const int a_kb  = (lane >> 4) * 16;
    const int b_row = wn * 64 + ((lane >> 4) << 3) + (lane & 7);
    const int b_kb  = ((lane >> 3) & 1) * 16;

#pragma unroll
    for (int s = 0; s < 2; s++) {
        cpa16(saA + s * STAGE_B,      Ab + s * BK3);
        cpa16(saA + s * STAGE_B + 16, Ab + s * BK3 + 8);
        cpa16(saB + s * STAGE_B,      Bb + s * BK3);
        cpa16(saB + s * STAGE_B + 16, Bb + s * BK3 + 8);
        cpa_commit();
    }

    for (int kt = 0; kt < NKIT; kt++) {
        cpa_wait<1>();
        __syncthreads();

        if (kt + 2 < NKIT) {
            const int ps = (kt + 2) % 3;
            const int k0 = (kt + 2) * BK3;
            cpa16(saA + ps * STAGE_B,      Ab + k0);
            cpa16(saA + ps * STAGE_B + 16, Ab + k0 + 8);
            cpa16(saB + ps * STAGE_B,      Bb + k0);
            cpa16(saB + ps * STAGE_B + 16, Bb + k0 + 8);
        }
        cpa_commit();

        const uint32_t sAs = sb + (kt % 3) * STAGE_B;
        const uint32_t sBs = sAs + ATILE_B;

#pragma unroll
        for (int kh = 0; kh < 2; kh++) {
            const int kbyte = kh * 32;
            uint32_t a[2][4];
#pragma unroll
            for (int mt = 0; mt < 2; mt++)
                ldsm_x4(a[mt][0], a[mt][1], a[mt][2], a[mt][3],
                        sAs + (a_row + mt * 16) * SROWB + kbyte + a_kb);
            uint32_t b[4][4];
#pragma unroll
            for (int nt = 0; nt < 4; nt++)
                ldsm_x4(b[nt][0], b[nt][1], b[nt][2], b[nt][3],
                        sBs + (b_row + nt * 16) * SROWB + kbyte + b_kb);
#pragma unroll
            for (int mt = 0; mt < 2; mt++)
#pragma unroll
                for (int j = 0; j < 8; j++)
                    mma_f16(acc[mt][j][0], acc[mt][j][1], acc[mt][j][2], acc[mt][j][3],
                            a[mt][0], a[mt][1], a[mt][2], a[mt][3],
                            b[j >> 1][(j & 1) * 2], b[j >> 1][(j & 1) * 2 + 1]);
        }
        __syncthreads();
    }

#pragma unroll
    for (int mt = 0; mt < 2; mt++) {
        int m0 = bm + wm * 32 + mt * 16 + (lane >> 2);
#pragma unroll
        for (int j = 0; j < 8; j++) {
            int n0 = bn + wn * 64 + j * 8 + (lane & 3) * 2;
            float2 v0 = { acc[mt][j][0], acc[mt][j][1] };
            float2 v1 = { acc[mt][j][2], acc[mt][j][3] };
            *(float2*)(C + (size_t)m0 * N + n0)       = v0;
            *(float2*)(C + (size_t)(m0 + 8) * N + n0) = v1;
        }
    }
}

// ---------------------------------------------------------------- RoPE on K region only (once)
__global__ void ropeK_kernel(float* __restrict__ qkv,
                             const float* __restrict__ cs, const float* __restrict__ sn)
{
    int idx = blockIdx.x * blockDim.x + threadIdx.x;   // MROWS*NKV*32
    int d = idx & 31;
    int h = (idx >> 5) & (NKV - 1);
    int r = idx >> 8;
    float c = cs[r * DH + d], s = sn[r * DH + d];
    float* p = qkv + (size_t)r * QKVDIM + HIDD + h * DH + d;
    float x1 = p[0], x2 = p[32];
    p[0]  = x1 * c - x2 * s;
    p[32] = x2 * c + x1 * s;
}

// ---------------------------------------------------------------- attention (R12, fp16 epilogue)
#define AQ 128
#define AK 32
#define KPAD 68
#define KPADB (KPAD * 4)
#define ABUF_B (AK * KPADB)
#define ASMEM (4 * ABUF_B)

__global__ __launch_bounds__(128) void attn_kernel(
    const float* __restrict__ QKV, const float* __restrict__ cs,
    const float* __restrict__ sn, __half* __restrict__ ATH)
{
    extern __shared__ __align__(16) float asmem[];
    const uint32_t sKb = smem_u32(asmem);
    const uint32_t sVb = sKb + 2 * ABUF_B;
    const float* KsF = asmem;
    const float* VsF = asmem + 2 * AK * KPAD;

    const int tid = threadIdx.x;
    const int b   = blockIdx.y >> 5;
    const int h   = blockIdx.y & 31;
    const int kvh = h >> 2;
    const int qt  = gridDim.x - 1 - blockIdx.x;
    const int qrow = qt * AQ + tid;

    const float scale = 0.125f;
    const float* qp  = QKV + (size_t)(b * SS + qrow) * QKVDIM + h * DH;
    const float* csq = cs + (size_t)(b * SS + qrow) * DH;
    const float* snq = sn + (size_t)(b * SS + qrow) * DH;

    u64t q2[DH / 2], o2[DH / 2];
#pragma unroll
    for (int d0 = 0; d0 < 32; d0 += 4) {
        float4 va = *(const float4*)(qp + d0);
        float4 vb = *(const float4*)(qp + d0 + 32);
        float4 cv = *(const float4*)(csq + d0);
        float4 sv = *(const float4*)(snq + d0);
        q2[d0 / 2]      = pack2((va.x*cv.x - vb.x*sv.x)*scale, (va.y*cv.y - vb.y*sv.y)*scale);
        q2[d0 / 2 + 1]  = pack2((va.z*cv.z - vb.z*sv.z)*scale, (va.w*cv.w - vb.w*sv.w)*scale);
        q2[d0 / 2 + 16] = pack2((vb.x*cv.x + va.x*sv.x)*scale, (vb.y*cv.y + va.y*sv.y)*scale);
        q2[d0 / 2 + 17] = pack2((vb.z*cv.z + va.z*sv.z)*scale, (vb.w*cv.w + va.w*sv.w)*scale);
    }
#pragma unroll
    for (int d = 0; d < DH / 2; d++) o2[d] = pack2(0.f, 0.f);

    float m = -1e30f, l = 0.f;
    const int ntiles = 4 * (qt + 1);

    const int lj   = tid >> 2;
    const int loff = (tid & 3) << 2;
    const float* kbase = QKV + (size_t)(b * SS + lj) * QKVDIM + HIDD + kvh * DH;

#pragma unroll
    for (int p = 0; p < 2; p++) {
        if (p < ntiles) {
            const float* kp = kbase + (size_t)p * AK * QKVDIM;
            const uint32_t kd = sKb + p * ABUF_B + lj * KPADB + (loff << 2);
            const uint32_t vd = sVb + p * ABUF_B + lj * KPADB + (loff << 2);
            cpa16(kd,       kp + loff);          cpa16(vd,       kp + KVDIM + loff);
            cpa16(kd + 64,  kp + loff + 16);     cpa16(vd + 64,  kp + KVDIM + loff + 16);
            cpa16(kd + 128, kp + loff + 32);     cpa16(vd + 128, kp + KVDIM + loff + 32);
            cpa16(kd + 192, kp + loff + 48);     cpa16(vd + 192, kp + KVDIM + loff + 48);
        }
        cpa_commit();
    }

    for (int t = 0; t < ntiles; t++) {
        cpa_wait<1>();
        __syncthreads();
        const int buf = t & 1;
        const int k0 = t * AK;
        const float* Kt = KsF + buf * AK * KPAD;
        const float* Vt = VsF + buf * AK * KPAD;

        float s[AK];
        float tmax = -1e30f;
#pragma unroll
        for (int j = 0; j < AK; j++) {
            u64t acc = pack2(0.f, 0.f);
#pragma unroll
            for (int d = 0; d < DH / 4; d++) {
                ulonglong2 kk2 = *(const ulonglong2*)&Kt[j * KPAD + 4 * d];
                acc = fma2(q2[2 * d + 0], kk2.x, acc);
                acc = fma2(q2[2 * d + 1], kk2.y, acc);
            }
            float alo, ahi;
            unpack2(acc, alo, ahi);
            float sc = alo + ahi;
            sc = (k0 + j <= qrow) ? sc : -1e30f;
            s[j] = sc;
            tmax = fmaxf(tmax, sc);
        }

        if (tmax > m) {
            float mn = tmax;
            float corr = __expf(m - mn);
            m = mn;
            l *= corr;
            u64t cd = pack_dup(corr);
#pragma unroll
            for (int d = 0; d < DH / 2; d++) o2[d] = mul2(o2[d], cd);
        }

#pragma unroll
        for (int j = 0; j < AK; j++) {
            float p = __expf(s[j] - m);
            l += p;
            u64t pd = pack_dup(p);
#pragma unroll
            for (int d = 0; d < DH / 4; d++) {
                ulonglong2 v2 = *(const ulonglong2*)&Vt[j * KPAD + 4 * d];
                o2[2 * d + 0] = fma2(pd, v2.x, o2[2 * d + 0]);
                o2[2 * d + 1] = fma2(pd, v2.y, o2[2 * d + 1]);
            }
        }

        __syncthreads();
        if (t + 2 < ntiles) {
            const float* kp = kbase + (size_t)(t + 2) * AK * QKVDIM;
            const uint32_t kd = sKb + buf * ABUF_B + lj * KPADB + (loff << 2);
            const uint32_t vd = sVb + buf * ABUF_B + lj * KPADB + (loff << 2);
            cpa16(kd,       kp + loff);          cpa16(vd,       kp + KVDIM + loff);
            cpa16(kd + 64,  kp + loff + 16);     cpa16(vd + 64,  kp + KVDIM + loff + 16);
            cpa16(kd + 128, kp + loff + 32);     cpa16(vd + 128, kp + KVDIM + loff + 32);
            cpa16(kd + 192, kp + loff + 48);     cpa16(vd + 192, kp + KVDIM + loff + 48);
        }
        cpa_commit();
    }

    // epilogue: normalize + single fp16 write
    const float inv = 1.f / l;
    __half* orow = ATH + (size_t)(b * SS + qrow) * KDIM + h * DH;
#pragma unroll
    for (int c = 0; c < DH; c += 8) {
        __half hb[8];
#pragma unroll
        for (int e = 0; e < 8; e += 2) {
            float v0, v1;
            unpack2(o2[(c + e) / 2], v0, v1);
            hb[e]     = __float2half(v0 * inv);
            hb[e + 1] = __float2half(v1 * inv);
        }
        *(uint4*)(orow + c) = *(const uint4*)hb;
    }
}

// ---------------------------------------------------------------- launch
extern "C" void kernel_launch(void* const* d_in, const int* in_sizes, int n_in,
                              void* d_out, int out_size)
{
    const float* hs = (const float*)d_in[0];
    const float* cs = (const float*)d_in[1];
    const float* sn = (const float*)d_in[2];
    const float* Wq = (const float*)d_in[4];
    const float* Wk = (const float*)d_in[5];
    const float* Wv = (const float*)d_in[6];
    const float* Wo = (const float*)d_in[7];
    float* out = (float*)d_out;

    float* qkv;
    cudaGetSymbolAddress((void**)&qkv, g_qkv);
    __half *hsh, *wh, *woh, *ath;
    cudaGetSymbolAddress((void**)&hsh, g_hs_h);
    cudaGetSymbolAddress((void**)&wh,  g_w_h);
    cudaGetSymbolAddress((void**)&woh, g_wo_h);
    cudaGetSymbolAddress((void**)&ath, g_at_h);

    cudaFuncSetAttribute(gemm_f16, cudaFuncAttributeMaxDynamicSharedMemorySize, GSMEM);
    cudaFuncSetAttribute(attn_kernel, cudaFuncAttributeMaxDynamicSharedMemorySize, ASMEM);

    const int nHS = MROWS * KDIM;
    const int nW  = (QKVDIM + HIDD) * KDIM;
    conv_kernel<<<(nHS + 255) / 256, 256>>>(hs, hsh, nHS);
    conv_w_kernel<<<(nW + 255) / 256, 256>>>(Wq, Wk, Wv, Wo, wh, woh);

    // merged QKV projection (single fp16 pass)
    gemm_f16<<<dim3(QKVDIM / 128, MROWS / 128), 256, GSMEM>>>(hsh, wh, qkv, QKVDIM);

    // K-RoPE (once), then fused attention (Q-RoPE + fp16 epilogue)
    const int kpairs = MROWS * NKV * (DH / 2);
    ropeK_kernel<<<kpairs / 256, 256>>>(qkv, cs, sn);
    attn_kernel<<<dim3(SS / AQ, BB * NH), dim3(128), ASMEM>>>(qkv, cs, sn, ath);

    // output projection (single fp16 pass)
    gemm_f16<<<dim3(HIDD / 128, MROWS / 128), 256, GSMEM>>>(ath, woh, out, HIDD);
}

// round 14
// speedup vs baseline: 6.0228x; 2.7605x over previous
#include <cuda_runtime.h>
#include <cuda_fp16.h>
#include <cstdint>
#include <math.h>

// ---------------------------------------------------------------- constants
#define BB   2
#define SS   2048
#define HIDD 2048
#define NH   32
#define NKV  8
#define DH   64
#define MROWS (BB*SS)        // 4096
#define KVDIM (NKV*DH)       // 512
#define KDIM  2048
#define QKVDIM (HIDD + 2*KVDIM)   // 3072

// ---------------------------------------------------------------- scratch
__device__ float  g_qkv [(size_t)MROWS * QKVDIM];   // 48 MB
__device__ __half g_hs_h[(size_t)MROWS * KDIM];     // 16 MB fp16(hs)
__device__ __half g_w_h [(size_t)QKVDIM * KDIM];    // 12 MB fp16(W) merged
__device__ __half g_wo_h[(size_t)HIDD  * KDIM];     //  8 MB
__device__ __half g_at_h[(size_t)MROWS * KDIM];     // 16 MB fp16(attn out)
__device__ __half g_kv16[(size_t)MROWS * 1024];     //  8 MB fp16 K|V (roped)

// ---------------------------------------------------------------- helpers
__device__ __forceinline__ uint32_t smem_u32(const void* p) {
    uint32_t a;
    asm("{ .reg .u64 t; cvta.to.shared.u64 t, %1; cvt.u32.u64 %0, t; }" : "=r"(a) : "l"(p));
    return a;
}
__device__ __forceinline__ void cpa16(uint32_t s, const void* g) {
    asm volatile("cp.async.cg.shared.global [%0], [%1], 16;" :: "r"(s), "l"(g));
}
__device__ __forceinline__ void cpa_commit() {
    asm volatile("cp.async.commit_group;" ::: "memory");
}
template<int N> __device__ __forceinline__ void cpa_wait() {
    asm volatile("cp.async.wait_group %0;" :: "n"(N) : "memory");
}
__device__ __forceinline__ void ldsm_x4(uint32_t& r0, uint32_t& r1, uint32_t& r2, uint32_t& r3,
                                        uint32_t addr) {
    asm volatile("ldmatrix.sync.aligned.m8n8.x4.shared.b16 {%0,%1,%2,%3}, [%4];"
                 : "=r"(r0), "=r"(r1), "=r"(r2), "=r"(r3) : "r"(addr));
}
__device__ __forceinline__ void ldsm_x4t(uint32_t& r0, uint32_t& r1, uint32_t& r2, uint32_t& r3,
                                         uint32_t addr) {
    asm volatile("ldmatrix.sync.aligned.m8n8.x4.trans.shared.b16 {%0,%1,%2,%3}, [%4];"
                 : "=r"(r0), "=r"(r1), "=r"(r2), "=r"(r3) : "r"(addr));
}
__device__ __forceinline__ void mma_f16(float& c0, float& c1, float& c2, float& c3,
                                        uint32_t a0, uint32_t a1, uint32_t a2, uint32_t a3,
                                        uint32_t b0, uint32_t b1) {
    asm volatile(
        "mma.sync.aligned.m16n8k16.row.col.f32.f16.f16.f32 "
        "{%0,%1,%2,%3}, {%4,%5,%6,%7}, {%8,%9}, {%0,%1,%2,%3};"
        : "+f"(c0), "+f"(c1), "+f"(c2), "+f"(c3)
        : "r"(a0), "r"(a1), "r"(a2), "r"(a3), "r"(b0), "r"(b1));
}

// ---------------------------------------------------------------- converts
__global__ void conv_kernel(const float* __restrict__ s, __half* __restrict__ d, int n) {
    int idx = blockIdx.x * blockDim.x + threadIdx.x;
    if (idx < n) d[idx] = __float2half(s[idx]);
}
__global__ void conv_w_kernel(const float* __restrict__ Wq, const float* __restrict__ Wk,
                              const float* __restrict__ Wv, const float* __restrict__ Wo,
                              __half* __restrict__ wh, __half* __restrict__ woh) {
    int idx = blockIdx.x * blockDim.x + threadIdx.x;
    if (idx >= (QKVDIM + HIDD) * KDIM) return;
    int r = idx >> 11;
    int k = idx & (KDIM - 1);
    float x;
    if (r < HIDD)                 x = Wq[(size_t)r * KDIM + k];
    else if (r < HIDD + KVDIM)    x = Wk[(size_t)(r - HIDD) * KDIM + k];
    else if (r < QKVDIM)          x = Wv[(size_t)(r - HIDD - KVDIM) * KDIM + k];
    else                          x = Wo[(size_t)(r - QKVDIM) * KDIM + k];
    if (r < QKVDIM) wh[idx] = __float2half(x);
    else            woh[(size_t)(r - QKVDIM) * KDIM + k] = __float2half(x);
}
// K|V region of qkv (post-ropeK) -> fp16 [row][1024]
__global__ void convKV_kernel(const float* __restrict__ qkv, __half* __restrict__ kv) {
    int idx = blockIdx.x * blockDim.x + threadIdx.x;
    if (idx >= MROWS * 1024) return;
    int r = idx >> 10, c = idx & 1023;
    kv[idx] = __float2half(qkv[(size_t)r * QKVDIM + HIDD + c]);
}

// ---------------------------------------------------------------- fp16 HMMA GEMM (R13 exact)
#define BK3   32
#define NKIT  (KDIM / BK3)       // 64
#define SROWB 80
#define ATILE_B (128 * SROWB)
#define STAGE_B (2 * ATILE_B)
#define GSMEM  (3 * STAGE_B)

__global__ __launch_bounds__(256, 2) void gemm_f16(
    const __half* __restrict__ A, const __half* __restrict__ B,
    float* __restrict__ C, int N)
{
    extern __shared__ __align__(128) char smem[];
    const uint32_t sb = smem_u32(smem);
    const int tid  = threadIdx.x;
    const int lane = tid & 31;
    const int wid  = tid >> 5;
    const int wm   = wid & 3;
    const int wn   = wid >> 2;
    const int bm = blockIdx.y * 128, bn = blockIdx.x * 128;

    const int lrow = tid >> 1;
    const int lc   = (tid & 1) * 2;
    const __half* Ab = A + (size_t)(bm + lrow) * KDIM + lc * 8;
    const __half* Bb = B + (size_t)(bn + lrow) * KDIM + lc * 8;
    const uint32_t saA = sb + lrow * SROWB + lc * 16;
    const uint32_t saB = sb + ATILE_B + lrow * SROWB + lc * 16;

    float acc[2][8][4];
#pragma unroll
    for (int i = 0; i < 2; i++)
#pragma unroll
        for (int j = 0; j < 8; j++)
#pragma unroll
            for (int r = 0; r < 4; r++) acc[i][j][r] = 0.f;

    const int a_row = wm * 32 + (lane & 15);
    const int a_kb  = (lane >> 4) * 16;
    const int b_row = wn * 64 + ((lane >> 4) << 3) + (lane & 7);
    const int b_kb  = ((lane >> 3) & 1) * 16;

#pragma unroll
    for (int s = 0; s < 2; s++) {
        cpa16(saA + s * STAGE_B,      Ab + s * BK3);
        cpa16(saA + s * STAGE_B + 16, Ab + s * BK3 + 8);
        cpa16(saB + s * STAGE_B,      Bb + s * BK3);
        cpa16(saB + s * STAGE_B + 16, Bb + s * BK3 + 8);
        cpa_commit();
    }

    for (int kt = 0; kt < NKIT; kt++) {
        cpa_wait<1>();
        __syncthreads();

        if (kt + 2 < NKIT) {
            const int ps = (kt + 2) % 3;
            const int k0 = (kt + 2) * BK3;
            cpa16(saA + ps * STAGE_B,      Ab + k0);
            cpa16(saA + ps * STAGE_B + 16, Ab + k0 + 8);
            cpa16(saB + ps * STAGE_B,      Bb + k0);
            cpa16(saB + ps * STAGE_B + 16, Bb + k0 + 8);
        }
        cpa_commit();

        const uint32_t sAs = sb + (kt % 3) * STAGE_B;
        const uint32_t sBs = sAs + ATILE_B;

#pragma unroll
        for (int kh = 0; kh < 2; kh++) {
            const int kbyte = kh * 32;
            uint32_t a[2][4];
#pragma unroll
            for (int mt = 0; mt < 2; mt++)
                ldsm_x4(a[mt][0], a[mt][1], a[mt][2], a[mt][3],
                        sAs + (a_row + mt * 16) * SROWB + kbyte + a_kb);
            uint32_t b[4][4];
#pragma unroll
            for (int nt = 0; nt < 4; nt++)
                ldsm_x4(b[nt][0], b[nt][1], b[nt][2], b[nt][3],
                        sBs + (b_row + nt * 16) * SROWB + kbyte + b_kb);
#pragma unroll
            for (int mt = 0; mt < 2; mt++)
#pragma unroll
                for (int j = 0; j < 8; j++)
                    mma_f16(acc[mt][j][0], acc[mt][j][1], acc[mt][j][2], acc[mt][j][3],
                            a[mt][0], a[mt][1], a[mt][2], a[mt][3],
                            b[j >> 1][(j & 1) * 2], b[j >> 1][(j & 1) * 2 + 1]);
        }
        __syncthreads();
    }

#pragma unroll
    for (int mt = 0; mt < 2; mt++) {
        int m0 = bm + wm * 32 + mt * 16 + (lane >> 2);
#pragma unroll
        for (int j = 0; j < 8; j++) {
            int n0 = bn + wn * 64 + j * 8 + (lane & 3) * 2;
            float2 v0 = { acc[mt][j][0], acc[mt][j][1] };
            float2 v1 = { acc[mt][j][2], acc[mt][j][3] };
            *(float2*)(C + (size_t)m0 * N + n0)       = v0;
            *(float2*)(C + (size_t)(m0 + 8) * N + n0) = v1;
        }
    }
}

// ---------------------------------------------------------------- RoPE on K region only (once)
__global__ void ropeK_kernel(float* __restrict__ qkv,
                             const float* __restrict__ cs, const float* __restrict__ sn)
{
    int idx = blockIdx.x * blockDim.x + threadIdx.x;
    int d = idx & 31;
    int h = (idx >> 5) & (NKV - 1);
    int r = idx >> 8;
    float c = cs[r * DH + d], s = sn[r * DH + d];
    float* p = qkv + (size_t)r * QKVDIM + HIDD + h * DH + d;
    float x1 = p[0], x2 = p[32];
    p[0]  = x1 * c - x2 * s;
    p[32] = x2 * c + x1 * s;
}

// ---------------------------------------------------------------- HMMA flash attention
// CTA = 64 q-rows of one head; 4 warps x 16 rows. Tiles of 64 keys, fp16 MMA,
// fp32 accum + fp32 softmax stats, causal mask on diagonal tile, LPT order.
#define QT 64
#define KT 64
#define PADH 72                       // halves per smem row (144 B)
#define KVBUF_B (KT * PADH * 2)       // 9216 B per buffer

__global__ __launch_bounds__(128) void attn_hmma(
    const float* __restrict__ QKV, const __half* __restrict__ KV,
    const float* __restrict__ cs, const float* __restrict__ sn,
    __half* __restrict__ ATH)
{
    __shared__ __half Qs[QT][PADH];         // 9216 B
    __shared__ __half Ks[2][KT][PADH];      // 18432 B
    __shared__ __half Vs[2][KT][PADH];      // 18432 B

    const int tid  = threadIdx.x;
    const int lane = tid & 31;
    const int w    = tid >> 5;
    const int b    = blockIdx.y >> 5;
    const int h    = blockIdx.y & 31;
    const int kvh  = h >> 2;
    const int qt   = gridDim.x - 1 - blockIdx.x;
    const int qbase = qt * QT;
    const int ntiles = qt + 1;

    const uint32_t sK = smem_u32(Ks);
    const uint32_t sV = smem_u32(Vs);
    const uint32_t sQ = smem_u32(Qs);

    // --- prefetch K/V tiles 0,1 (2 threads per key row, 64B each)
    const int lrow = tid >> 1;
    const int lch  = (tid & 1) * 4;
    const __half* kg = KV + ((size_t)(b * SS) + lrow) * 1024 + kvh * DH;
#pragma unroll
    for (int p = 0; p < 2; p++) {
        if (p < ntiles) {
            const __half* kgp = kg + (size_t)p * KT * 1024;
            uint32_t kd = sK + p * KVBUF_B + lrow * 144 + lch * 16;
            uint32_t vd = sV + p * KVBUF_B + lrow * 144 + lch * 16;
#pragma unroll
            for (int c = 0; c < 4; c++) {
                cpa16(kd + c * 16, kgp + (lch + c) * 8);
                cpa16(vd + c * 16, kgp + 512 + (lch + c) * 8);
            }
        }
        cpa_commit();
    }

    // --- Q load + RoPE + scale -> fp16 smem (2 threads per row)
    {
        const int row = tid >> 1;
        const int hs  = tid & 1;                // column half
        const int grow = qbase + row;
        const float* qp = QKV + ((size_t)(b * SS + grow)) * QKVDIM + h * DH;
        const float* cp = cs + (size_t)(b * SS + grow) * DH;
        const float* sp = sn + (size_t)(b * SS + grow) * DH;
#pragma unroll
        for (int i = 0; i < 8; i++) {
            int d0 = hs * 32 + i * 4;
            float4 xv = *(const float4*)(qp + d0);
            float4 pv = *(const float4*)(qp + (d0 ^ 32));
            float4 cv = *(const float4*)(cp + d0);
            float4 sv = *(const float4*)(sp + d0);
            float o0, o1, o2, o3;
            if (hs == 0) {
                o0 = (xv.x*cv.x - pv.x*sv.x)*0.125f; o1 = (xv.y*cv.y - pv.y*sv.y)*0.125f;
                o2 = (xv.z*cv.z - pv.z*sv.z)*0.125f; o3 = (xv.w*cv.w - pv.w*sv.w)*0.125f;
            } else {
                o0 = (xv.x*cv.x + pv.x*sv.x)*0.125f; o1 = (xv.y*cv.y + pv.y*sv.y)*0.125f;
                o2 = (xv.z*cv.z + pv.z*sv.z)*0.125f; o3 = (xv.w*cv.w + pv.w*sv.w)*0.125f;
            }
            *(__half2*)&Qs[row][d0]     = __floats2half2_rn(o0, o1);
            *(__half2*)&Qs[row][d0 + 2] = __floats2half2_rn(o2, o3);
        }
    }
    __syncthreads();

    // --- Q fragments (resident)
    uint32_t Qf[4][4];
    {
        const int a_row = w * 16 + (lane & 15);
        const int a_kb  = (lane >> 4) * 16;     // bytes
#pragma unroll
        for (int ks = 0; ks < 4; ks++)
            ldsm_x4(Qf[ks][0], Qf[ks][1], Qf[ks][2], Qf[ks][3],
                    sQ + a_row * 144 + ks * 32 + a_kb);
    }

    float O[8][4];
#pragma unroll
    for (int j = 0; j < 8; j++)
#pragma unroll
        for (int r = 0; r < 4; r++) O[j][r] = 0.f;
    float m0 = -1e30f, m1 = -1e30f, l0 = 0.f, l1 = 0.f;

    const int bKrow = ((lane >> 4) << 3) + (lane & 7);
    const int bKb   = ((lane >> 3) & 1) * 16;
    const int vm = lane >> 3, vr = lane & 7;
    const int grow0 = qbase + w * 16 + (lane >> 2);

    for (int t = 0; t < ntiles; t++) {
        cpa_wait<1>();
        __syncthreads();
        const int buf = t & 1;
        const uint32_t sKb2 = sK + buf * KVBUF_B;
        const uint32_t sVb2 = sV + buf * KVBUF_B;

        // S = Q @ K^T
        float S[8][4];
#pragma unroll
        for (int j = 0; j < 8; j++)
#pragma unroll
            for (int r = 0; r < 4; r++) S[j][r] = 0.f;
#pragma unroll
        for (int ks = 0; ks < 4; ks++) {
            uint32_t bk[4][4];
#pragma unroll
            for (int nt = 0; nt < 4; nt++)
                ldsm_x4(bk[nt][0], bk[nt][1], bk[nt][2], bk[nt][3],
                        sKb2 + (bKrow + nt * 16) * 144 + ks * 32 + bKb);
#pragma unroll
            for (int j = 0; j < 8; j++)
                mma_f16(S[j][0], S[j][1], S[j][2], S[j][3],
                        Qf[ks][0], Qf[ks][1], Qf[ks][2], Qf[ks][3],
                        bk[j >> 1][(j & 1) * 2], bk[j >> 1][(j & 1) * 2 + 1]);
        }

        // causal mask (diagonal tile only)
        if (t == ntiles - 1) {
#pragma unroll
            for (int j = 0; j < 8; j++) {
                int col = t * KT + j * 8 + 2 * (lane & 3);
                if (col     > grow0)     S[j][0] = -1e30f;
                if (col + 1 > grow0)     S[j][1] = -1e30f;
                if (col     > grow0 + 8) S[j][2] = -1e30f;
                if (col + 1 > grow0 + 8) S[j][3] = -1e30f;
            }
        }

        // row stats (rows grow0 / grow0+8, shared by 4 lanes)
        float t0 = -1e30f, t1 = -1e30f;
#pragma unroll
        for (int j = 0; j < 8; j++) {
            t0 = fmaxf(t0, fmaxf(S[j][0], S[j][1]));
            t1 = fmaxf(t1, fmaxf(S[j][2], S[j][3]));
        }
        t0 = fmaxf(t0, __shfl_xor_sync(0xffffffffu, t0, 1));
        t0 = fmaxf(t0, __shfl_xor_sync(0xffffffffu, t0, 2));
        t1 = fmaxf(t1, __shfl_xor_sync(0xffffffffu, t1, 1));
        t1 = fmaxf(t1, __shfl_xor_sync(0xffffffffu, t1, 2));
        float nm0 = fmaxf(m0, t0), nm1 = fmaxf(m1, t1);
        float cr0 = __expf(m0 - nm0), cr1 = __expf(m1 - nm1);
        m0 = nm0; m1 = nm1;
        l0 *= cr0; l1 *= cr1;
#pragma unroll
        for (int j = 0; j < 8; j++) {
            O[j][0] *= cr0; O[j][1] *= cr0;
            O[j][2] *= cr1; O[j][3] *= cr1;
        }

        // P = exp(S - m), fp16 A-frags + row sums
        uint32_t Pa[8], Pb[8];
        float s0 = 0.f, s1 = 0.f;
#pragma unroll
        for (int j = 0; j < 8; j++) {
            float p0 = __expf(S[j][0] - m0), p1 = __expf(S[j][1] - m0);
            float p2 = __expf(S[j][2] - m1), p3 = __expf(S[j][3] - m1);
            s0 += p0 + p1; s1 += p2 + p3;
            __half2 ha = __floats2half2_rn(p0, p1);
            __half2 hb = __floats2half2_rn(p2, p3);
            Pa[j] = *(uint32_t*)&ha;
            Pb[j] = *(uint32_t*)&hb;
        }
        s0 += __shfl_xor_sync(0xffffffffu, s0, 1);
        s0 += __shfl_xor_sync(0xffffffffu, s0, 2);
        s1 += __shfl_xor_sync(0xffffffffu, s1, 1);
        s1 += __shfl_xor_sync(0xffffffffu, s1, 2);
        l0 += s0; l1 += s1;

        // O += P @ V
#pragma unroll
        for (int ks = 0; ks < 4; ks++) {
#pragma unroll
            for (int np = 0; np < 4; np++) {
                uint32_t v0, v1, v2, v3;
                ldsm_x4t(v0, v1, v2, v3,
                         sVb2 + (ks * 16 + (vm & 1) * 8 + vr) * 144
                              + (np * 16 + (vm >> 1) * 8) * 2);
                mma_f16(O[2*np][0], O[2*np][1], O[2*np][2], O[2*np][3],
                        Pa[2*ks], Pb[2*ks], Pa[2*ks+1], Pb[2*ks+1], v0, v1);
                mma_f16(O[2*np+1][0], O[2*np+1][1], O[2*np+1][2], O[2*np+1][3],
                        Pa[2*ks], Pb[2*ks], Pa[2*ks+1], Pb[2*ks+1], v2, v3);
            }
        }

        __syncthreads();
        if (t + 2 < ntiles) {
            const __half* kgp = kg + (size_t)(t + 2) * KT * 1024;
            uint32_t kd = sK + buf * KVBUF_B + lrow * 144 + lch * 16;
            uint32_t vd = sV + buf * KVBUF_B + lrow * 144 + lch * 16;
#pragma unroll
            for (int c = 0; c < 4; c++) {
                cpa16(kd + c * 16, kgp + (lch + c) * 8);
                cpa16(vd + c * 16, kgp + 512 + (lch + c) * 8);
            }
        }
        cpa_commit();
    }

    // --- epilogue: normalize + fp16 store
    const float i0 = 1.f / l0, i1 = 1.f / l1;
    __half* o0p = ATH + ((size_t)(b * SS + grow0)) * KDIM + h * DH + 2 * (lane & 3);
    __half* o1p = o0p + (size_t)8 * KDIM;
#pragma unroll
    for (int j = 0; j < 8; j++) {
        __half2 h01 = __floats2half2_rn(O[j][0] * i0, O[j][1] * i0);
        __half2 h23 = __floats2half2_rn(O[j][2] * i1, O[j][3] * i1);
        *(__half2*)(o0p + j * 8) = h01;
        *(__half2*)(o1p + j * 8) = h23;
    }
}

// ---------------------------------------------------------------- launch
extern "C" void kernel_launch(void* const* d_in, const int* in_sizes, int n_in,
                              void* d_out, int out_size)
{
    const float* hs = (const float*)d_in[0];
    const float* cs = (const float*)d_in[1];
    const float* sn = (const float*)d_in[2];
    const float* Wq = (const float*)d_in[4];
    const float* Wk = (const float*)d_in[5];
    const float* Wv = (const float*)d_in[6];
    const float* Wo = (const float*)d_in[7];
    float* out = (float*)d_out;

    float* qkv;
    cudaGetSymbolAddress((void**)&qkv, g_qkv);
    __half *hsh, *wh, *woh, *ath, *kv16;
    cudaGetSymbolAddress((void**)&hsh,  g_hs_h);
    cudaGetSymbolAddress((void**)&wh,   g_w_h);
    cudaGetSymbolAddress((void**)&woh,  g_wo_h);
    cudaGetSymbolAddress((void**)&ath,  g_at_h);
    cudaGetSymbolAddress((void**)&kv16, g_kv16);

    cudaFuncSetAttribute(gemm_f16, cudaFuncAttributeMaxDynamicSharedMemorySize, GSMEM);

    const int nHS = MROWS * KDIM;
    const int nW  = (QKVDIM + HIDD) * KDIM;
    conv_kernel<<<(nHS + 255) / 256, 256>>>(hs, hsh, nHS);
    conv_w_kernel<<<(nW + 255) / 256, 256>>>(Wq, Wk, Wv, Wo, wh, woh);

    // merged QKV projection
    gemm_f16<<<dim3(QKVDIM / 128, MROWS / 128), 256, GSMEM>>>(hsh, wh, qkv, QKVDIM);

    // K-RoPE (fp32), convert K|V to fp16
    const int kpairs = MROWS * NKV * (DH / 2);
    ropeK_kernel<<<kpairs / 256, 256>>>(qkv, cs, sn);
    convKV_kernel<<<(MROWS * 1024 + 255) / 256, 256>>>(qkv, kv16);

    // HMMA flash attention (Q-RoPE fused)
    attn_hmma<<<dim3(SS / QT, BB * NH), dim3(128)>>>(qkv, kv16, cs, sn, ath);

    // output projection
    gemm_f16<<<dim3(HIDD / 128, MROWS / 128), 256, GSMEM>>>(ath, woh, out, HIDD);
}

// round 15
// speedup vs baseline: 6.3893x; 1.0608x over previous
#include <cuda_runtime.h>
#include <cuda_fp16.h>
#include <cstdint>
#include <math.h>

// ---------------------------------------------------------------- constants
#define BB   2
#define SS   2048
#define HIDD 2048
#define NH   32
#define NKV  8
#define DH   64
#define MROWS (BB*SS)        // 4096
#define KVDIM (NKV*DH)       // 512
#define KDIM  2048
#define QKVDIM (HIDD + 2*KVDIM)   // 3072

// ---------------------------------------------------------------- scratch
__device__ float  g_qkv [(size_t)MROWS * QKVDIM];   // 48 MB
__device__ __half g_hs_h[(size_t)MROWS * KDIM];     // 16 MB fp16(hs)
__device__ __half g_w_h [(size_t)QKVDIM * KDIM];    // 12 MB fp16(W) merged
__device__ __half g_wo_h[(size_t)HIDD  * KDIM];     //  8 MB
__device__ __half g_at_h[(size_t)MROWS * KDIM];     // 16 MB fp16(attn out)
__device__ __half g_kv16[(size_t)MROWS * 1024];     //  8 MB fp16 K|V (roped)

// ---------------------------------------------------------------- helpers
__device__ __forceinline__ uint32_t smem_u32(const void* p) {
    uint32_t a;
    asm("{ .reg .u64 t; cvta.to.shared.u64 t, %1; cvt.u32.u64 %0, t; }" : "=r"(a) : "l"(p));
    return a;
}
__device__ __forceinline__ void cpa16(uint32_t s, const void* g) {
    asm volatile("cp.async.cg.shared.global [%0], [%1], 16;" :: "r"(s), "l"(g));
}
__device__ __forceinline__ void cpa_commit() {
    asm volatile("cp.async.commit_group;" ::: "memory");
}
template<int N> __device__ __forceinline__ void cpa_wait() {
    asm volatile("cp.async.wait_group %0;" :: "n"(N) : "memory");
}
__device__ __forceinline__ void ldsm_x4(uint32_t& r0, uint32_t& r1, uint32_t& r2, uint32_t& r3,
                                        uint32_t addr) {
    asm volatile("ldmatrix.sync.aligned.m8n8.x4.shared.b16 {%0,%1,%2,%3}, [%4];"
                 : "=r"(r0), "=r"(r1), "=r"(r2), "=r"(r3) : "r"(addr));
}
__device__ __forceinline__ void ldsm_x4t(uint32_t& r0, uint32_t& r1, uint32_t& r2, uint32_t& r3,
                                         uint32_t addr) {
    asm volatile("ldmatrix.sync.aligned.m8n8.x4.trans.shared.b16 {%0,%1,%2,%3}, [%4];"
                 : "=r"(r0), "=r"(r1), "=r"(r2), "=r"(r3) : "r"(addr));
}
__device__ __forceinline__ void mma_f16(float& c0, float& c1, float& c2, float& c3,
                                        uint32_t a0, uint32_t a1, uint32_t a2, uint32_t a3,
                                        uint32_t b0, uint32_t b1) {
    asm volatile(
        "mma.sync.aligned.m16n8k16.row.col.f32.f16.f16.f32 "
        "{%0,%1,%2,%3}, {%4,%5,%6,%7}, {%8,%9}, {%0,%1,%2,%3};"
        : "+f"(c0), "+f"(c1), "+f"(c2), "+f"(c3)
        : "r"(a0), "r"(a1), "r"(a2), "r"(a3), "r"(b0), "r"(b1));
}

// ---------------------------------------------------------------- converts
__global__ void conv_kernel(const float* __restrict__ s, __half* __restrict__ d, int n) {
    int idx = blockIdx.x * blockDim.x + threadIdx.x;
    if (idx < n) d[idx] = __float2half(s[idx]);
}
__global__ void conv_w_kernel(const float* __restrict__ Wq, const float* __restrict__ Wk,
                              const float* __restrict__ Wv, const float* __restrict__ Wo,
                              __half* __restrict__ wh, __half* __restrict__ woh) {
    int idx = blockIdx.x * blockDim.x + threadIdx.x;
    if (idx >= (QKVDIM + HIDD) * KDIM) return;
    int r = idx >> 11;
    int k = idx & (KDIM - 1);
    float x;
    if (r < HIDD)                 x = Wq[(size_t)r * KDIM + k];
    else if (r < HIDD + KVDIM)    x = Wk[(size_t)(r - HIDD) * KDIM + k];
    else if (r < QKVDIM)          x = Wv[(size_t)(r - HIDD - KVDIM) * KDIM + k];
    else                          x = Wo[(size_t)(r - QKVDIM) * KDIM + k];
    if (r < QKVDIM) wh[idx] = __float2half(x);
    else            woh[(size_t)(r - QKVDIM) * KDIM + k] = __float2half(x);
}
// Fused: rope K (fp32 read from qkv) -> fp16 kv buffer; convert V -> fp16.
__global__ void ropeKV_kernel(const float* __restrict__ qkv,
                              const float* __restrict__ cs, const float* __restrict__ sn,
                              __half* __restrict__ kv) {
    int idx = blockIdx.x * blockDim.x + threadIdx.x;   // MROWS*512 threads
    const int KP = MROWS * 256;                        // K pairs
    if (idx < KP) {
        int d = idx & 31;
        int h = (idx >> 5) & (NKV - 1);
        int r = idx >> 8;
        float c = cs[r * DH + d], s = sn[r * DH + d];
        const float* p = qkv + (size_t)r * QKVDIM + HIDD + h * DH + d;
        float x1 = p[0], x2 = p[32];
        kv[(size_t)r * 1024 + h * DH + d]      = __float2half(x1 * c - x2 * s);
        kv[(size_t)r * 1024 + h * DH + d + 32] = __float2half(x2 * c + x1 * s);
    } else {
        int e = idx - KP;                              // V: 2 elements per thread
        int r = e >> 8;
        int c2 = (e & 255) * 2;
        const float* p = qkv + (size_t)r * QKVDIM + HIDD + 512 + c2;
        kv[(size_t)r * 1024 + 512 + c2]     = __float2half(p[0]);
        kv[(size_t)r * 1024 + 512 + c2 + 1] = __float2half(p[1]);
    }
}

// ---------------------------------------------------------------- fp16 HMMA GEMM (R13/R14 exact)
#define BK3   32
#define NKIT  (KDIM / BK3)       // 64
#define SROWB 80
#define ATILE_B (128 * SROWB)
#define STAGE_B (2 * ATILE_B)
#define GSMEM  (3 * STAGE_B)

__global__ __launch_bounds__(256, 2) void gemm_f16(
    const __half* __restrict__ A, const __half* __restrict__ B,
    float* __restrict__ C, int N)
{
    extern __shared__ __align__(128) char smem[];
    const uint32_t sb = smem_u32(smem);
    const int tid  = threadIdx.x;
    const int lane = tid & 31;
    const int wid  = tid >> 5;
    const int wm   = wid & 3;
    const int wn   = wid >> 2;
    const int bm = blockIdx.y * 128, bn = blockIdx.x * 128;

    const int lrow = tid >> 1;
    const int lc   = (tid & 1) * 2;
    const __half* Ab = A + (size_t)(bm + lrow) * KDIM + lc * 8;
    const __half* Bb = B + (size_t)(bn + lrow) * KDIM + lc * 8;
    const uint32_t saA = sb + lrow * SROWB + lc * 16;
    const uint32_t saB = sb + ATILE_B + lrow * SROWB + lc * 16;

    float acc[2][8][4];
#pragma unroll
    for (int i = 0; i < 2; i++)
#pragma unroll
        for (int j = 0; j < 8; j++)
#pragma unroll
            for (int r = 0; r < 4; r++) acc[i][j][r] = 0.f;

    const int a_row = wm * 32 + (lane & 15);
    const int a_kb  = (lane >> 4) * 16;
    const int b_row = wn * 64 + ((lane >> 4) << 3) + (lane & 7);
    const int b_kb  = ((lane >> 3) & 1) * 16;

#pragma unroll
    for (int s = 0; s < 2; s++) {
        cpa16(saA + s * STAGE_B,      Ab + s * BK3);
        cpa16(saA + s * STAGE_B + 16, Ab + s * BK3 + 8);
        cpa16(saB + s * STAGE_B,      Bb + s * BK3);
        cpa16(saB + s * STAGE_B + 16, Bb + s * BK3 + 8);
        cpa_commit();
    }

    for (int kt = 0; kt < NKIT; kt++) {
        cpa_wait<1>();
        __syncthreads();

        if (kt + 2 < NKIT) {
            const int ps = (kt + 2) % 3;
            const int k0 = (kt + 2) * BK3;
            cpa16(saA + ps * STAGE_B,      Ab + k0);
            cpa16(saA + ps * STAGE_B + 16, Ab + k0 + 8);
            cpa16(saB + ps * STAGE_B,      Bb + k0);
            cpa16(saB + ps * STAGE_B + 16, Bb + k0 + 8);
        }
        cpa_commit();

        const uint32_t sAs = sb + (kt % 3) * STAGE_B;
        const uint32_t sBs = sAs + ATILE_B;

#pragma unroll
        for (int kh = 0; kh < 2; kh++) {
            const int kbyte = kh * 32;
            uint32_t a[2][4];
#pragma unroll
            for (int mt = 0; mt < 2; mt++)
                ldsm_x4(a[mt][0], a[mt][1], a[mt][2], a[mt][3],
                        sAs + (a_row + mt * 16) * SROWB + kbyte + a_kb);
            uint32_t b[4][4];
#pragma unroll
            for (int nt = 0; nt < 4; nt++)
                ldsm_x4(b[nt][0], b[nt][1], b[nt][2], b[nt][3],
                        sBs + (b_row + nt * 16) * SROWB + kbyte + b_kb);
#pragma unroll
            for (int mt = 0; mt < 2; mt++)
#pragma unroll
                for (int j = 0; j < 8; j++)
                    mma_f16(acc[mt][j][0], acc[mt][j][1], acc[mt][j][2], acc[mt][j][3],
                            a[mt][0], a[mt][1], a[mt][2], a[mt][3],
                            b[j >> 1][(j & 1) * 2], b[j >> 1][(j & 1) * 2 + 1]);
        }
        __syncthreads();
    }

#pragma unroll
    for (int mt = 0; mt < 2; mt++) {
        int m0 = bm + wm * 32 + mt * 16 + (lane >> 2);
#pragma unroll
        for (int j = 0; j < 8; j++) {
            int n0 = bn + wn * 64 + j * 8 + (lane & 3) * 2;
            float2 v0 = { acc[mt][j][0], acc[mt][j][1] };
            float2 v1 = { acc[mt][j][2], acc[mt][j][3] };
            *(float2*)(C + (size_t)m0 * N + n0)       = v0;
            *(float2*)(C + (size_t)(m0 + 8) * N + n0) = v1;
        }
    }
}

// ---------------------------------------------------------------- HMMA flash attention
// CTA = 128 q-rows of one head; 8 warps x 16 rows; 64-key double-buffered tiles.
#define QT 128
#define KT 64
#define PADH 72                       // halves per smem row (144 B)
#define QBUF_B (QT * PADH * 2)        // 18432 B
#define KVBUF_B (KT * PADH * 2)       // 9216 B per buffer
#define ASMEM (QBUF_B + 4 * KVBUF_B)  // 55296 B

__global__ __launch_bounds__(256) void attn_hmma(
    const float* __restrict__ QKV, const __half* __restrict__ KV,
    const float* __restrict__ cs, const float* __restrict__ sn,
    __half* __restrict__ ATH)
{
    extern __shared__ __align__(16) char asmem[];
    const uint32_t sQ = smem_u32(asmem);
    const uint32_t sK = sQ + QBUF_B;
    const uint32_t sV = sK + 2 * KVBUF_B;

    const int tid  = threadIdx.x;
    const int lane = tid & 31;
    const int w    = tid >> 5;
    const int b    = blockIdx.y >> 5;
    const int h    = blockIdx.y & 31;
    const int kvh  = h >> 2;
    const int qt   = gridDim.x - 1 - blockIdx.x;
    const int qbase = qt * QT;
    const int ntiles = 2 * (qt + 1);

    // --- prefetch K/V tiles 0,1 (4 threads per key row, 2x16B chunks each)
    const int lrow = tid >> 2;          // 0..63
    const int lch  = (tid & 3) * 2;     // chunk pair
    const __half* kgK = KV + ((size_t)(b * SS) + lrow) * 1024 + kvh * DH;
    const __half* kgV = kgK + 512;
#pragma unroll
    for (int p = 0; p < 2; p++) {
        {
            const size_t off = (size_t)p * KT * 1024;
            uint32_t kd = sK + p * KVBUF_B + lrow * 144;
            uint32_t vd = sV + p * KVBUF_B + lrow * 144;
#pragma unroll
            for (int c = 0; c < 2; c++) {
                int ch = lch + c;
                cpa16(kd + ch * 16, kgK + off + ch * 8);
                cpa16(vd + ch * 16, kgV + off + ch * 8);
            }
        }
        cpa_commit();
    }

    // --- Q load + RoPE + scale -> fp16 smem (2 threads per row)
    {
        const int row = tid >> 1;           // 0..127
        const int hs  = tid & 1;
        const int grow = qbase + row;
        const float* qp = QKV + ((size_t)(b * SS + grow)) * QKVDIM + h * DH;
        const float* cp = cs + (size_t)(b * SS + grow) * DH;
        const float* sp = sn + (size_t)(b * SS + grow) * DH;
        __half* qrow = (__half*)(asmem) + row * PADH;
#pragma unroll
        for (int i = 0; i < 8; i++) {
            int d0 = hs * 32 + i * 4;
            float4 xv = *(const float4*)(qp + d0);
            float4 pv = *(const float4*)(qp + (d0 ^ 32));
            float4 cv = *(const float4*)(cp + d0);
            float4 sv = *(const float4*)(sp + d0);
            float o0, o1, o2, o3;
            if (hs == 0) {
                o0 = (xv.x*cv.x - pv.x*sv.x)*0.125f; o1 = (xv.y*cv.y - pv.y*sv.y)*0.125f;
                o2 = (xv.z*cv.z - pv.z*sv.z)*0.125f; o3 = (xv.w*cv.w - pv.w*sv.w)*0.125f;
            } else {
                o0 = (xv.x*cv.x + pv.x*sv.x)*0.125f; o1 = (xv.y*cv.y + pv.y*sv.y)*0.125f;
                o2 = (xv.z*cv.z + pv.z*sv.z)*0.125f; o3 = (xv.w*cv.w + pv.w*sv.w)*0.125f;
            }
            *(__half2*)(qrow + d0)     = __floats2half2_rn(o0, o1);
            *(__half2*)(qrow + d0 + 2) = __floats2half2_rn(o2, o3);
        }
    }
    __syncthreads();

    // --- Q fragments (resident, warp w covers rows w*16..w*16+15)
    uint32_t Qf[4][4];
    {
        const int a_row = w * 16 + (lane & 15);
        const int a_kb  = (lane >> 4) * 16;
#pragma unroll
        for (int ks = 0; ks < 4; ks++)
            ldsm_x4(Qf[ks][0], Qf[ks][1], Qf[ks][2], Qf[ks][3],
                    sQ + a_row * 144 + ks * 32 + a_kb);
    }

    float O[8][4];
#pragma unroll
    for (int j = 0; j < 8; j++)
#pragma unroll
        for (int r = 0; r < 4; r++) O[j][r] = 0.f;
    float m0 = -1e30f, m1 = -1e30f, l0 = 0.f, l1 = 0.f;

    const int bKrow = ((lane >> 4) << 3) + (lane & 7);
    const int bKb   = ((lane >> 3) & 1) * 16;
    const int vm = lane >> 3, vr = lane & 7;
    const int grow0 = qbase + w * 16 + (lane >> 2);

    for (int t = 0; t < ntiles; t++) {
        cpa_wait<1>();
        __syncthreads();
        const int buf = t & 1;
        const uint32_t sKb2 = sK + buf * KVBUF_B;
        const uint32_t sVb2 = sV + buf * KVBUF_B;

        // S = Q @ K^T
        float S[8][4];
#pragma unroll
        for (int j = 0; j < 8; j++)
#pragma unroll
            for (int r = 0; r < 4; r++) S[j][r] = 0.f;
#pragma unroll
        for (int ks = 0; ks < 4; ks++) {
            uint32_t bk[4][4];
#pragma unroll
            for (int nt = 0; nt < 4; nt++)
                ldsm_x4(bk[nt][0], bk[nt][1], bk[nt][2], bk[nt][3],
                        sKb2 + (bKrow + nt * 16) * 144 + ks * 32 + bKb);
#pragma unroll
            for (int j = 0; j < 8; j++)
                mma_f16(S[j][0], S[j][1], S[j][2], S[j][3],
                        Qf[ks][0], Qf[ks][1], Qf[ks][2], Qf[ks][3],
                        bk[j >> 1][(j & 1) * 2], bk[j >> 1][(j & 1) * 2 + 1]);
        }

        // causal mask (last two tiles can cross the diagonal)
        if (t >= ntiles - 2) {
#pragma unroll
            for (int j = 0; j < 8; j++) {
                int col = t * KT + j * 8 + 2 * (lane & 3);
                if (col     > grow0)     S[j][0] = -1e30f;
                if (col + 1 > grow0)     S[j][1] = -1e30f;
                if (col     > grow0 + 8) S[j][2] = -1e30f;
                if (col + 1 > grow0 + 8) S[j][3] = -1e30f;
            }
        }

        // row stats
        float t0 = -1e30f, t1 = -1e30f;
#pragma unroll
        for (int j = 0; j < 8; j++) {
            t0 = fmaxf(t0, fmaxf(S[j][0], S[j][1]));
            t1 = fmaxf(t1, fmaxf(S[j][2], S[j][3]));
        }
        t0 = fmaxf(t0, __shfl_xor_sync(0xffffffffu, t0, 1));
        t0 = fmaxf(t0, __shfl_xor_sync(0xffffffffu, t0, 2));
        t1 = fmaxf(t1, __shfl_xor_sync(0xffffffffu, t1, 1));
        t1 = fmaxf(t1, __shfl_xor_sync(0xffffffffu, t1, 2));
        float nm0 = fmaxf(m0, t0), nm1 = fmaxf(m1, t1);
        float cr0 = __expf(m0 - nm0), cr1 = __expf(m1 - nm1);
        m0 = nm0; m1 = nm1;
        l0 *= cr0; l1 *= cr1;
#pragma unroll
        for (int j = 0; j < 8; j++) {
            O[j][0] *= cr0; O[j][1] *= cr0;
            O[j][2] *= cr1; O[j][3] *= cr1;
        }

        // P = exp(S - m)
        uint32_t Pa[8], Pb[8];
        float s0 = 0.f, s1 = 0.f;
#pragma unroll
        for (int j = 0; j < 8; j++) {
            float p0 = __expf(S[j][0] - m0), p1 = __expf(S[j][1] - m0);
            float p2 = __expf(S[j][2] - m1), p3 = __expf(S[j][3] - m1);
            s0 += p0 + p1; s1 += p2 + p3;
            __half2 ha = __floats2half2_rn(p0, p1);
            __half2 hb = __floats2half2_rn(p2, p3);
            Pa[j] = *(uint32_t*)&ha;
            Pb[j] = *(uint32_t*)&hb;
        }
        s0 += __shfl_xor_sync(0xffffffffu, s0, 1);
        s0 += __shfl_xor_sync(0xffffffffu, s0, 2);
        s1 += __shfl_xor_sync(0xffffffffu, s1, 1);
        s1 += __shfl_xor_sync(0xffffffffu, s1, 2);
        l0 += s0; l1 += s1;

        // O += P @ V
#pragma unroll
        for (int ks = 0; ks < 4; ks++) {
#pragma unroll
            for (int np = 0; np < 4; np++) {
                uint32_t v0, v1, v2, v3;
                ldsm_x4t(v0, v1, v2, v3,
                         sVb2 + (ks * 16 + (vm & 1) * 8 + vr) * 144
                              + (np * 16 + (vm >> 1) * 8) * 2);
                mma_f16(O[2*np][0], O[2*np][1], O[2*np][2], O[2*np][3],
                        Pa[2*ks], Pb[2*ks], Pa[2*ks+1], Pb[2*ks+1], v0, v1);
                mma_f16(O[2*np+1][0], O[2*np+1][1], O[2*np+1][2], O[2*np+1][3],
                        Pa[2*ks], Pb[2*ks], Pa[2*ks+1], Pb[2*ks+1], v2, v3);
            }
        }

        __syncthreads();
        if (t + 2 < ntiles) {
            const size_t off = (size_t)(t + 2) * KT * 1024;
            uint32_t kd = sK + buf * KVBUF_B + lrow * 144;
            uint32_t vd = sV + buf * KVBUF_B + lrow * 144;
#pragma unroll
            for (int c = 0; c < 2; c++) {
                int ch = lch + c;
                cpa16(kd + ch * 16, kgK + off + ch * 8);
                cpa16(vd + ch * 16, kgV + off + ch * 8);
            }
        }
        cpa_commit();
    }

    // --- epilogue: normalize + fp16 store
    const float i0 = 1.f / l0, i1 = 1.f / l1;
    __half* o0p = ATH + ((size_t)(b * SS + grow0)) * KDIM + h * DH + 2 * (lane & 3);
    __half* o1p = o0p + (size_t)8 * KDIM;
#pragma unroll
    for (int j = 0; j < 8; j++) {
        __half2 h01 = __floats2half2_rn(O[j][0] * i0, O[j][1] * i0);
        __half2 h23 = __floats2half2_rn(O[j][2] * i1, O[j][3] * i1);
        *(__half2*)(o0p + j * 8) = h01;
        *(__half2*)(o1p + j * 8) = h23;
    }
}

// ---------------------------------------------------------------- launch
extern "C" void kernel_launch(void* const* d_in, const int* in_sizes, int n_in,
                              void* d_out, int out_size)
{
    const float* hs = (const float*)d_in[0];
    const float* cs = (const float*)d_in[1];
    const float* sn = (const float*)d_in[2];
    const float* Wq = (const float*)d_in[4];
    const float* Wk = (const float*)d_in[5];
    const float* Wv = (const float*)d_in[6];
    const float* Wo = (const float*)d_in[7];
    float* out = (float*)d_out;

    float* qkv;
    cudaGetSymbolAddress((void**)&qkv, g_qkv);
    __half *hsh, *wh, *woh, *ath, *kv16;
    cudaGetSymbolAddress((void**)&hsh,  g_hs_h);
    cudaGetSymbolAddress((void**)&wh,   g_w_h);
    cudaGetSymbolAddress((void**)&woh,  g_wo_h);
    cudaGetSymbolAddress((void**)&ath,  g_at_h);
    cudaGetSymbolAddress((void**)&kv16, g_kv16);

    cudaFuncSetAttribute(gemm_f16, cudaFuncAttributeMaxDynamicSharedMemorySize, GSMEM);
    cudaFuncSetAttribute(attn_hmma, cudaFuncAttributeMaxDynamicSharedMemorySize, ASMEM);

    const int nHS = MROWS * KDIM;
    const int nW  = (QKVDIM + HIDD) * KDIM;
    conv_kernel<<<(nHS + 255) / 256, 256>>>(hs, hsh, nHS);
    conv_w_kernel<<<(nW + 255) / 256, 256>>>(Wq, Wk, Wv, Wo, wh, woh);

    // merged QKV projection
    gemm_f16<<<dim3(QKVDIM / 128, MROWS / 128), 256, GSMEM>>>(hsh, wh, qkv, QKVDIM);

    // fused K-RoPE + KV fp16 convert
    ropeKV_kernel<<<(MROWS * 512) / 256, 256>>>(qkv, cs, sn, kv16);

    // HMMA flash attention (Q-RoPE fused), QT=128
    attn_hmma<<<dim3(SS / QT, BB * NH), dim3(256), ASMEM>>>(qkv, kv16, cs, sn, ath);

    // output projection
    gemm_f16<<<dim3(HIDD / 128, MROWS / 128), 256, GSMEM>>>(ath, woh, out, HIDD);
}